// round 1
// baseline (speedup 1.0000x reference)
#include <cuda_runtime.h>

// Problem constants (fixed by the reference)
#define N_NODES 50000
#define N_EDGES 800000
#define F_IN    64
#define H       128
#define L_LAYERS 4
#define G_GRAPHS 64
#define C_OUT   10
#define TAB     4096          // filter-table grid points per layer
#define GAMMA_C 10.0f

// ---------------- scratch (device globals: allocation-free) ----------------
__device__ float g_proj[N_NODES * H];
__device__ float g_agg [N_NODES * H];
__device__ float g_cur [N_NODES * H];
__device__ float g_table[L_LAYERS * TAB * H];
__device__ float g_pool[G_GRAPHS * H];
__device__ float g_cnt [G_GRAPHS];

// ---------------- small helpers ----------------
__global__ void zero4_kernel(float4* __restrict__ p, int n4) {
    int i = blockIdx.x * blockDim.x + threadIdx.x;
    if (i < n4) p[i] = make_float4(0.f, 0.f, 0.f, 0.f);
}

__global__ void zero_pool_kernel() {
    int i = blockIdx.x * blockDim.x + threadIdx.x;
    if (i < G_GRAPHS * H) g_pool[i] = 0.f;
    if (i < G_GRAPHS)     g_cnt[i]  = 0.f;
}

// shifted softplus: log(1+exp(v)) - log(2), numerically stable
__device__ __forceinline__ float ssp(float v) {
    return fmaxf(v, 0.f) + log1pf(expf(-fabsf(v))) - 0.69314718056f;
}

// ---------------- filter table build ----------------
// table[l][k][j] = ( ssp( rbf(d_k) @ Wf1_l + bf1_l ) @ Wf2_l + bf2_l )[j]
// d_k = k/(TAB-1), rbf_i(d) = exp(-gamma*(d - i/(H-1))^2)
__global__ void table_kernel(const float* __restrict__ Wf1, const float* __restrict__ bf1,
                             const float* __restrict__ Wf2, const float* __restrict__ bf2) {
    const int ROWS = 32;
    const int chunks = TAB / ROWS;
    int l  = blockIdx.x / chunks;
    int k0 = (blockIdx.x % chunks) * ROWS;
    int j  = threadIdx.x;                       // 128 threads

    __shared__ float rbf[H];
    __shared__ float hid[H];

    const float* w1 = Wf1 + (size_t)l * H * H;
    const float* w2 = Wf2 + (size_t)l * H * H;
    float b1v = bf1[l * H + j];
    float b2v = bf2[l * H + j];
    float cj  = j * (1.0f / (H - 1));

    for (int r = 0; r < ROWS; r++) {
        int k = k0 + r;
        float d = k * (1.0f / (TAB - 1));
        float u = d - cj;
        rbf[j] = expf(-GAMMA_C * u * u);
        __syncthreads();

        float acc = b1v;
        #pragma unroll 8
        for (int i = 0; i < H; i++) acc = fmaf(rbf[i], w1[(size_t)i * H + j], acc);
        float sp = ssp(acc);
        __syncthreads();
        hid[j] = sp;
        __syncthreads();

        float acc2 = b2v;
        #pragma unroll 8
        for (int i = 0; i < H; i++) acc2 = fmaf(hid[i], w2[(size_t)i * H + j], acc2);
        g_table[((size_t)l * TAB + k) * H + j] = acc2;
        __syncthreads();
    }
}

// ---------------- node GEMM: C[M,128] = A[M,K] @ B[K,128] + bias (opt relu) ----------------
// BM=64, BN=128, BK=16, 256 threads. Warp w owns rows w*8..w*8+7; lane owns cols lane*4..+3.
template <int KDIM, bool RELU>
__global__ void gemm_kernel(const float* __restrict__ A, const float* __restrict__ B,
                            const float* __restrict__ bias, float* __restrict__ C, int M) {
    __shared__ float As[16][65];
    __shared__ float Bs[16][128];

    int tid  = threadIdx.x;
    int w    = tid >> 5;
    int lane = tid & 31;
    int r0   = blockIdx.x * 64;

    float acc[8][4];
    #pragma unroll
    for (int i = 0; i < 8; i++)
        #pragma unroll
        for (int j = 0; j < 4; j++) acc[i][j] = 0.f;

    for (int kk = 0; kk < KDIM; kk += 16) {
        // load A tile 64x16 (one float4 per thread)
        int ar  = tid >> 2;     // 0..63
        int ak4 = tid & 3;      // 0..3
        float4 av = make_float4(0.f, 0.f, 0.f, 0.f);
        int arow = r0 + ar;
        if (arow < M)
            av = *(const float4*)(A + (size_t)arow * KDIM + kk + ak4 * 4);
        As[ak4 * 4 + 0][ar] = av.x;
        As[ak4 * 4 + 1][ar] = av.y;
        As[ak4 * 4 + 2][ar] = av.z;
        As[ak4 * 4 + 3][ar] = av.w;

        // load B tile 16x128 (two float4 per thread)
        int bk = tid >> 5;
        int bc = (tid & 31) * 4;
        *(float4*)&Bs[bk][bc]     = *(const float4*)(B + (size_t)(kk + bk)     * H + bc);
        *(float4*)&Bs[bk + 8][bc] = *(const float4*)(B + (size_t)(kk + bk + 8) * H + bc);
        __syncthreads();

        #pragma unroll
        for (int k = 0; k < 16; k++) {
            float4 b4 = *(const float4*)&Bs[k][lane * 4];
            #pragma unroll
            for (int i = 0; i < 8; i++) {
                float a = As[k][w * 8 + i];
                acc[i][0] = fmaf(a, b4.x, acc[i][0]);
                acc[i][1] = fmaf(a, b4.y, acc[i][1]);
                acc[i][2] = fmaf(a, b4.z, acc[i][2]);
                acc[i][3] = fmaf(a, b4.w, acc[i][3]);
            }
        }
        __syncthreads();
    }

    float4 bv = *(const float4*)(bias + lane * 4);
    #pragma unroll
    for (int i = 0; i < 8; i++) {
        int row = r0 + w * 8 + i;
        if (row < M) {
            float4 o;
            o.x = acc[i][0] + bv.x;
            o.y = acc[i][1] + bv.y;
            o.z = acc[i][2] + bv.z;
            o.w = acc[i][3] + bv.w;
            if (RELU) {
                o.x = fmaxf(o.x, 0.f); o.y = fmaxf(o.y, 0.f);
                o.z = fmaxf(o.z, 0.f); o.w = fmaxf(o.w, 0.f);
            }
            *(float4*)(C + (size_t)row * H + lane * 4) = o;
        }
    }
}

// ---------------- edge kernel: gather-gate-scatter with table lerp ----------------
// one warp per edge; lane handles 4 of the 128 channels
__global__ void edge_kernel(const float* __restrict__ table,   // [TAB][H] for this layer
                            const float* __restrict__ proj,    // [N][H]
                            const float* __restrict__ dist,
                            const int*   __restrict__ src,
                            const int*   __restrict__ dst,
                            float*       __restrict__ agg, int E) {
    int e = blockIdx.x * 8 + (threadIdx.x >> 5);
    if (e >= E) return;
    int lane = threadIdx.x & 31;

    float d = __ldg(dist + e);
    int  s  = __ldg(src + e);
    int  t  = __ldg(dst + e);

    float pos = d * (float)(TAB - 1);
    int k = (int)pos;
    if (k < 0) k = 0;
    if (k > TAB - 2) k = TAB - 2;
    float fr = pos - (float)k;

    const float4* trow = (const float4*)(table + (size_t)k * H) + lane;
    float4 f0 = __ldg(trow);
    float4 f1 = __ldg(trow + (H / 4));
    float4 hs = __ldg((const float4*)(proj + (size_t)s * H) + lane);

    float4 m;
    m.x = (f0.x + fr * (f1.x - f0.x)) * hs.x;
    m.y = (f0.y + fr * (f1.y - f0.y)) * hs.y;
    m.z = (f0.z + fr * (f1.z - f0.z)) * hs.z;
    m.w = (f0.w + fr * (f1.w - f0.w)) * hs.w;

    float* out = agg + (size_t)t * H + lane * 4;
    atomicAdd(out + 0, m.x);
    atomicAdd(out + 1, m.y);
    atomicAdd(out + 2, m.z);
    atomicAdd(out + 3, m.w);
}

// ---------------- graph pooling (sum + count) ----------------
__global__ void pool_kernel(const float* __restrict__ cur, const int* __restrict__ gid, int N) {
    int n = blockIdx.x * 8 + (threadIdx.x >> 5);
    if (n >= N) return;
    int lane = threadIdx.x & 31;
    int g = __ldg(gid + n);
    float4 v = __ldg((const float4*)(cur + (size_t)n * H) + lane);
    float* p = g_pool + (size_t)g * H + lane * 4;
    atomicAdd(p + 0, v.x);
    atomicAdd(p + 1, v.y);
    atomicAdd(p + 2, v.z);
    atomicAdd(p + 3, v.w);
    if (lane == 0) atomicAdd(&g_cnt[g], 1.0f);
}

// ---------------- readout: mean, FC, log_softmax ----------------
__global__ void readout_kernel(const float* __restrict__ fcw, const float* __restrict__ fcb,
                               float* __restrict__ out) {
    int g = blockIdx.x;
    int t = threadIdx.x;    // 128
    __shared__ float p[H];
    __shared__ float logits[C_OUT];

    float c = fmaxf(g_cnt[g], 1.0f);
    p[t] = g_pool[(size_t)g * H + t] / c;
    __syncthreads();

    if (t < C_OUT) {
        float acc = fcb[t];
        #pragma unroll 8
        for (int h = 0; h < H; h++) acc = fmaf(p[h], fcw[h * C_OUT + t], acc);
        logits[t] = acc;
    }
    __syncthreads();

    if (t == 0) {
        float mx = -1e30f;
        for (int i = 0; i < C_OUT; i++) mx = fmaxf(mx, logits[i]);
        float se = 0.f;
        for (int i = 0; i < C_OUT; i++) se += expf(logits[i] - mx);
        float lse = mx + logf(se);
        for (int i = 0; i < C_OUT; i++) out[g * C_OUT + i] = logits[i] - lse;
    }
}

// ---------------- launch ----------------
extern "C" void kernel_launch(void* const* d_in, const int* in_sizes, int n_in,
                              void* d_out, int out_size) {
    const float* x         = (const float*)d_in[0];
    const float* edge_dist = (const float*)d_in[1];
    const int*   esrc      = (const int*)  d_in[2];
    const int*   edst      = (const int*)  d_in[3];
    const int*   gid       = (const int*)  d_in[4];
    const float* W1_0      = (const float*)d_in[5];
    const float* b1_0      = (const float*)d_in[6];
    const float* W1_rest   = (const float*)d_in[7];
    const float* b1_rest   = (const float*)d_in[8];
    const float* Wf1       = (const float*)d_in[9];
    const float* bf1       = (const float*)d_in[10];
    const float* Wf2       = (const float*)d_in[11];
    const float* bf2       = (const float*)d_in[12];
    const float* W2        = (const float*)d_in[13];
    const float* b2        = (const float*)d_in[14];
    const float* fcw       = (const float*)d_in[15];
    const float* fcb       = (const float*)d_in[16];
    float* out = (float*)d_out;

    int E = in_sizes[1];
    int N = in_sizes[4];

    float *proj, *agg, *cur, *table;
    cudaGetSymbolAddress((void**)&proj,  g_proj);
    cudaGetSymbolAddress((void**)&agg,   g_agg);
    cudaGetSymbolAddress((void**)&cur,   g_cur);
    cudaGetSymbolAddress((void**)&table, g_table);

    // build per-layer filter tables (8 MB, L2-resident)
    table_kernel<<<L_LAYERS * (TAB / 32), H>>>(Wf1, bf1, Wf2, bf2);

    int gemm_blocks = (N + 63) / 64;
    int nh4 = (N * H) / 4;
    int zero_blocks = (nh4 + 255) / 256;
    int edge_blocks = (E + 7) / 8;

    for (int l = 0; l < L_LAYERS; l++) {
        // node projection
        if (l == 0)
            gemm_kernel<F_IN, false><<<gemm_blocks, 256>>>(x, W1_0, b1_0, proj, N);
        else
            gemm_kernel<H, false><<<gemm_blocks, 256>>>(
                cur, W1_rest + (size_t)(l - 1) * H * H, b1_rest + (size_t)(l - 1) * H, proj, N);

        // zero accumulator
        zero4_kernel<<<zero_blocks, 256>>>((float4*)agg, nh4);

        // gather-gate-scatter over edges
        edge_kernel<<<edge_blocks, 256>>>(table + (size_t)l * TAB * H,
                                          proj, edge_dist, esrc, edst, agg, E);

        // output projection + relu
        gemm_kernel<H, true><<<gemm_blocks, 256>>>(
            agg, W2 + (size_t)l * H * H, b2 + (size_t)l * H, cur, N);
    }

    // graph mean pooling + FC + log_softmax
    zero_pool_kernel<<<(G_GRAPHS * H + 255) / 256, 256>>>();
    pool_kernel<<<(N + 7) / 8, 256>>>(cur, gid, N);
    readout_kernel<<<G_GRAPHS, H>>>(fcw, fcb, out);
}

// round 2
// speedup vs baseline: 1.6766x; 1.6766x over previous
#include <cuda_runtime.h>
#include <cuda_fp16.h>

// Problem constants (fixed by the reference)
#define N_NODES 50000
#define N_EDGES 800000
#define F_IN    64
#define H       128
#define L_LAYERS 4
#define G_GRAPHS 64
#define C_OUT   10
#define TAB     4096          // filter-table grid points per layer
#define GAMMA_C 10.0f

// ---------------- scratch (device globals: allocation-free) ----------------
__device__ float  g_proj[N_NODES * H];
__device__ float  g_agg [N_NODES * H];
__device__ float  g_cur [N_NODES * H];
__device__ __half g_table[L_LAYERS * TAB * H];   // fp16 filter table (4 MB)
__device__ float  g_pool[G_GRAPHS * H];
__device__ float  g_cnt [G_GRAPHS];

// ---------------- small helpers ----------------
__global__ void zero4_kernel(float4* __restrict__ p, int n4) {
    int i = blockIdx.x * blockDim.x + threadIdx.x;
    if (i < n4) p[i] = make_float4(0.f, 0.f, 0.f, 0.f);
}

__global__ void zero_pool_kernel() {
    int i = blockIdx.x * blockDim.x + threadIdx.x;
    if (i < G_GRAPHS * H) g_pool[i] = 0.f;
    if (i < G_GRAPHS)     g_cnt[i]  = 0.f;
}

// shifted softplus: log(1+exp(v)) - log(2), numerically stable
__device__ __forceinline__ float ssp(float v) {
    return fmaxf(v, 0.f) + log1pf(expf(-fabsf(v))) - 0.69314718056f;
}

__device__ __forceinline__ unsigned f2tf32(float x) {
    unsigned u;
    asm("cvt.rna.tf32.f32 %0, %1;" : "=r"(u) : "f"(x));
    return u;
}

// ---------------- filter table build ----------------
// table[l][k][j] = ( ssp( rbf(d_k) @ Wf1_l + bf1_l ) @ Wf2_l + bf2_l )[j]
__global__ void table_kernel(const float* __restrict__ Wf1, const float* __restrict__ bf1,
                             const float* __restrict__ Wf2, const float* __restrict__ bf2) {
    const int ROWS = 32;
    const int chunks = TAB / ROWS;
    int l  = blockIdx.x / chunks;
    int k0 = (blockIdx.x % chunks) * ROWS;
    int j  = threadIdx.x;                       // 128 threads

    __shared__ float rbf[H];
    __shared__ float hid[H];

    const float* w1 = Wf1 + (size_t)l * H * H;
    const float* w2 = Wf2 + (size_t)l * H * H;
    float b1v = bf1[l * H + j];
    float b2v = bf2[l * H + j];
    float cj  = j * (1.0f / (H - 1));

    for (int r = 0; r < ROWS; r++) {
        int k = k0 + r;
        float d = k * (1.0f / (TAB - 1));
        float u = d - cj;
        rbf[j] = expf(-GAMMA_C * u * u);
        __syncthreads();

        float acc = b1v;
        #pragma unroll 8
        for (int i = 0; i < H; i++) acc = fmaf(rbf[i], w1[(size_t)i * H + j], acc);
        float sp = ssp(acc);
        __syncthreads();
        hid[j] = sp;
        __syncthreads();

        float acc2 = b2v;
        #pragma unroll 8
        for (int i = 0; i < H; i++) acc2 = fmaf(hid[i], w2[(size_t)i * H + j], acc2);
        g_table[((size_t)l * TAB + k) * H + j] = __float2half_rn(acc2);
        __syncthreads();
    }
}

// ---------------- tf32 tensor-core GEMM ----------------
// C[M,128] = A[M,KDIM] @ B[KDIM,128] + bias (optional relu)
// CTA tile 128x128, BK=32, 256 threads = 8 warps (2 m x 4 n), warp tile 64x32.
// mma.sync.aligned.m16n8k8 tf32.
#define BM 128
#define BN 128
#define BKT 32
#define AS_STRIDE 36
#define BS_STRIDE 132

template <int KDIM, bool RELU>
__global__ void __launch_bounds__(256) gemm_tf32(const float* __restrict__ A,
                                                 const float* __restrict__ B,
                                                 const float* __restrict__ bias,
                                                 float* __restrict__ C, int M) {
    __shared__ float As[BM * AS_STRIDE];   // [m][k], stride 36, values are tf32 bit patterns
    __shared__ float Bs[BKT * BS_STRIDE];  // [k][n], stride 132

    int tid  = threadIdx.x;
    int lane = tid & 31;
    int wid  = tid >> 5;
    int wm   = wid >> 2;          // 0..1  -> row block of 64
    int wn   = wid & 3;           // 0..3  -> col block of 32
    int r0   = blockIdx.x * BM;

    int grp  = lane >> 2;         // 0..7
    int thr4 = lane & 3;          // 0..3

    float c[4][4][4];             // [am][an][reg]
    #pragma unroll
    for (int i = 0; i < 4; i++)
        #pragma unroll
        for (int j = 0; j < 4; j++)
            #pragma unroll
            for (int r = 0; r < 4; r++) c[i][j][r] = 0.f;

    for (int kk = 0; kk < KDIM; kk += BKT) {
        // ---- stage A tile (128x32) : 1024 float4, 4 per thread ----
        #pragma unroll
        for (int j = 0; j < 4; j++) {
            int idx = tid + j * 256;
            int row = idx >> 3;          // 0..127
            int k4  = idx & 7;           // 0..7
            float4 v = make_float4(0.f, 0.f, 0.f, 0.f);
            int ga = r0 + row;
            if (ga < M) v = *(const float4*)(A + (size_t)ga * KDIM + kk + k4 * 4);
            float* dst = As + row * AS_STRIDE + k4 * 4;
            dst[0] = __uint_as_float(f2tf32(v.x));
            dst[1] = __uint_as_float(f2tf32(v.y));
            dst[2] = __uint_as_float(f2tf32(v.z));
            dst[3] = __uint_as_float(f2tf32(v.w));
        }
        // ---- stage B tile (32x128) : 1024 float4, 4 per thread ----
        #pragma unroll
        for (int j = 0; j < 4; j++) {
            int idx = tid + j * 256;
            int k   = idx >> 5;          // 0..31
            int n4  = idx & 31;          // 0..31
            float4 v = *(const float4*)(B + (size_t)(kk + k) * H + n4 * 4);
            float* dst = Bs + k * BS_STRIDE + n4 * 4;
            dst[0] = __uint_as_float(f2tf32(v.x));
            dst[1] = __uint_as_float(f2tf32(v.y));
            dst[2] = __uint_as_float(f2tf32(v.z));
            dst[3] = __uint_as_float(f2tf32(v.w));
        }
        __syncthreads();

        #pragma unroll
        for (int ks = 0; ks < BKT / 8; ks++) {
            // load A fragments: 4 m-atoms
            unsigned a[4][4];
            #pragma unroll
            for (int am = 0; am < 4; am++) {
                int m0 = wm * 64 + am * 16;
                const float* base = As + (size_t)(m0 + grp) * AS_STRIDE + ks * 8 + thr4;
                a[am][0] = __float_as_uint(base[0]);
                a[am][1] = __float_as_uint(base[8 * AS_STRIDE]);
                a[am][2] = __float_as_uint(base[4]);
                a[am][3] = __float_as_uint(base[8 * AS_STRIDE + 4]);
            }
            // load B fragments: 4 n-atoms
            unsigned b[4][2];
            #pragma unroll
            for (int an = 0; an < 4; an++) {
                int n0 = wn * 32 + an * 8;
                const float* base = Bs + (size_t)(ks * 8 + thr4) * BS_STRIDE + n0 + grp;
                b[an][0] = __float_as_uint(base[0]);
                b[an][1] = __float_as_uint(base[4 * BS_STRIDE]);
            }
            #pragma unroll
            for (int am = 0; am < 4; am++)
                #pragma unroll
                for (int an = 0; an < 4; an++) {
                    asm volatile(
                        "mma.sync.aligned.m16n8k8.row.col.f32.tf32.tf32.f32 "
                        "{%0,%1,%2,%3}, {%4,%5,%6,%7}, {%8,%9}, {%0,%1,%2,%3};"
                        : "+f"(c[am][an][0]), "+f"(c[am][an][1]),
                          "+f"(c[am][an][2]), "+f"(c[am][an][3])
                        : "r"(a[am][0]), "r"(a[am][1]), "r"(a[am][2]), "r"(a[am][3]),
                          "r"(b[an][0]), "r"(b[an][1]));
                }
        }
        __syncthreads();
    }

    // ---- epilogue ----
    #pragma unroll
    for (int an = 0; an < 4; an++) {
        int col = wn * 32 + an * 8 + 2 * thr4;
        float2 bv = *(const float2*)(bias + col);
        #pragma unroll
        for (int am = 0; am < 4; am++) {
            int row0 = r0 + wm * 64 + am * 16 + grp;
            float2 o0, o1;
            o0.x = c[am][an][0] + bv.x;  o0.y = c[am][an][1] + bv.y;
            o1.x = c[am][an][2] + bv.x;  o1.y = c[am][an][3] + bv.y;
            if (RELU) {
                o0.x = fmaxf(o0.x, 0.f); o0.y = fmaxf(o0.y, 0.f);
                o1.x = fmaxf(o1.x, 0.f); o1.y = fmaxf(o1.y, 0.f);
            }
            if (row0 < M)     *(float2*)(C + (size_t)row0 * H + col)       = o0;
            if (row0 + 8 < M) *(float2*)(C + (size_t)(row0 + 8) * H + col) = o1;
        }
    }
}

// ---------------- edge kernel: gather-gate-scatter with fp16 table lerp ----------------
// one warp per edge; lane handles 4 of the 128 channels
__global__ void edge_kernel(const __half* __restrict__ table,  // [TAB][H] for this layer
                            const float* __restrict__ proj,    // [N][H]
                            const float* __restrict__ dist,
                            const int*   __restrict__ src,
                            const int*   __restrict__ dst,
                            float*       __restrict__ agg, int E) {
    int e = blockIdx.x * 8 + (threadIdx.x >> 5);
    if (e >= E) return;
    int lane = threadIdx.x & 31;

    float d = __ldg(dist + e);
    int  s  = __ldg(src + e);
    int  t  = __ldg(dst + e);

    float pos = d * (float)(TAB - 1);
    int k = (int)pos;
    if (k < 0) k = 0;
    if (k > TAB - 2) k = TAB - 2;
    float fr = pos - (float)k;

    // 4 channels per lane = 8 bytes of fp16 per table row
    const uint2* trow = (const uint2*)(table + (size_t)k * H) + lane;
    uint2 q0 = __ldg(trow);
    uint2 q1 = __ldg(trow + (H / 4));   // next row (H halves = H/4 uint2)
    float4 hs = __ldg((const float4*)(proj + (size_t)s * H) + lane);

    float2 f0a = __half22float2(*(const __half2*)&q0.x);
    float2 f0b = __half22float2(*(const __half2*)&q0.y);
    float2 f1a = __half22float2(*(const __half2*)&q1.x);
    float2 f1b = __half22float2(*(const __half2*)&q1.y);

    float mx = (f0a.x + fr * (f1a.x - f0a.x)) * hs.x;
    float my = (f0a.y + fr * (f1a.y - f0a.y)) * hs.y;
    float mz = (f0b.x + fr * (f1b.x - f0b.x)) * hs.z;
    float mw = (f0b.y + fr * (f1b.y - f0b.y)) * hs.w;

    float* out = agg + (size_t)t * H + lane * 4;
    asm volatile("red.global.add.v4.f32 [%0], {%1,%2,%3,%4};"
                 :: "l"(out), "f"(mx), "f"(my), "f"(mz), "f"(mw) : "memory");
}

// ---------------- graph pooling (sum + count) ----------------
__global__ void pool_kernel(const float* __restrict__ cur, const int* __restrict__ gid, int N) {
    int n = blockIdx.x * 8 + (threadIdx.x >> 5);
    if (n >= N) return;
    int lane = threadIdx.x & 31;
    int g = __ldg(gid + n);
    float4 v = __ldg((const float4*)(cur + (size_t)n * H) + lane);
    float* p = g_pool + (size_t)g * H + lane * 4;
    asm volatile("red.global.add.v4.f32 [%0], {%1,%2,%3,%4};"
                 :: "l"(p), "f"(v.x), "f"(v.y), "f"(v.z), "f"(v.w) : "memory");
    if (lane == 0) atomicAdd(&g_cnt[g], 1.0f);
}

// ---------------- readout: mean, FC, log_softmax ----------------
__global__ void readout_kernel(const float* __restrict__ fcw, const float* __restrict__ fcb,
                               float* __restrict__ out) {
    int g = blockIdx.x;
    int t = threadIdx.x;    // 128
    __shared__ float p[H];
    __shared__ float logits[C_OUT];

    float c = fmaxf(g_cnt[g], 1.0f);
    p[t] = g_pool[(size_t)g * H + t] / c;
    __syncthreads();

    if (t < C_OUT) {
        float acc = fcb[t];
        #pragma unroll 8
        for (int h = 0; h < H; h++) acc = fmaf(p[h], fcw[h * C_OUT + t], acc);
        logits[t] = acc;
    }
    __syncthreads();

    if (t == 0) {
        float mx = -1e30f;
        for (int i = 0; i < C_OUT; i++) mx = fmaxf(mx, logits[i]);
        float se = 0.f;
        for (int i = 0; i < C_OUT; i++) se += expf(logits[i] - mx);
        float lse = mx + logf(se);
        for (int i = 0; i < C_OUT; i++) out[g * C_OUT + i] = logits[i] - lse;
    }
}

// ---------------- launch ----------------
extern "C" void kernel_launch(void* const* d_in, const int* in_sizes, int n_in,
                              void* d_out, int out_size) {
    const float* x         = (const float*)d_in[0];
    const float* edge_dist = (const float*)d_in[1];
    const int*   esrc      = (const int*)  d_in[2];
    const int*   edst      = (const int*)  d_in[3];
    const int*   gid       = (const int*)  d_in[4];
    const float* W1_0      = (const float*)d_in[5];
    const float* b1_0      = (const float*)d_in[6];
    const float* W1_rest   = (const float*)d_in[7];
    const float* b1_rest   = (const float*)d_in[8];
    const float* Wf1       = (const float*)d_in[9];
    const float* bf1       = (const float*)d_in[10];
    const float* Wf2       = (const float*)d_in[11];
    const float* bf2       = (const float*)d_in[12];
    const float* W2        = (const float*)d_in[13];
    const float* b2        = (const float*)d_in[14];
    const float* fcw       = (const float*)d_in[15];
    const float* fcb       = (const float*)d_in[16];
    float* out = (float*)d_out;

    int E = in_sizes[1];
    int N = in_sizes[4];

    float *proj, *agg, *cur;
    __half* table;
    cudaGetSymbolAddress((void**)&proj,  g_proj);
    cudaGetSymbolAddress((void**)&agg,   g_agg);
    cudaGetSymbolAddress((void**)&cur,   g_cur);
    cudaGetSymbolAddress((void**)&table, g_table);

    // build per-layer filter tables (fp16, 4 MB, L2-resident)
    table_kernel<<<L_LAYERS * (TAB / 32), H>>>(Wf1, bf1, Wf2, bf2);

    int gemm_blocks = (N + BM - 1) / BM;
    int nh4 = (N * H) / 4;
    int zero_blocks = (nh4 + 255) / 256;
    int edge_blocks = (E + 7) / 8;

    for (int l = 0; l < L_LAYERS; l++) {
        // node projection (tf32 tensor cores)
        if (l == 0)
            gemm_tf32<F_IN, false><<<gemm_blocks, 256>>>(x, W1_0, b1_0, proj, N);
        else
            gemm_tf32<H, false><<<gemm_blocks, 256>>>(
                cur, W1_rest + (size_t)(l - 1) * H * H, b1_rest + (size_t)(l - 1) * H, proj, N);

        // zero accumulator
        zero4_kernel<<<zero_blocks, 256>>>((float4*)agg, nh4);

        // gather-gate-scatter over edges
        edge_kernel<<<edge_blocks, 256>>>(table + (size_t)l * TAB * H,
                                          proj, edge_dist, esrc, edst, agg, E);

        // output projection + relu (tf32 tensor cores)
        gemm_tf32<H, true><<<gemm_blocks, 256>>>(
            agg, W2 + (size_t)l * H * H, b2 + (size_t)l * H, cur, N);
    }

    // graph mean pooling + FC + log_softmax
    zero_pool_kernel<<<(G_GRAPHS * H + 255) / 256, 256>>>();
    pool_kernel<<<(N + 7) / 8, 256>>>(cur, gid, N);
    readout_kernel<<<G_GRAPHS, H>>>(fcw, fcb, out);
}

// round 3
// speedup vs baseline: 1.7150x; 1.0229x over previous
#include <cuda_runtime.h>
#include <cuda_fp16.h>

// Problem constants (fixed by the reference)
#define N_NODES 50000
#define N_EDGES 800000
#define F_IN    64
#define H       128
#define L_LAYERS 4
#define G_GRAPHS 64
#define C_OUT   10
#define TAB     4096          // filter-table grid points per layer
#define GAMMA_C 10.0f

// ---------------- scratch (device globals: allocation-free) ----------------
__device__ __half g_proj[N_NODES * H];           // fp16 projected nodes (edge-gather source)
__device__ float  g_agg [N_NODES * H];
__device__ float  g_cur [N_NODES * H];
__device__ __half g_table[L_LAYERS * TAB * H];   // fp16 filter table (4 MB)
__device__ float  g_pool[G_GRAPHS * H];
__device__ float  g_cnt [G_GRAPHS];

// ---------------- small helpers ----------------
__global__ void zero4_kernel(float4* __restrict__ p, int n4) {
    int i = blockIdx.x * blockDim.x + threadIdx.x;
    if (i < n4) p[i] = make_float4(0.f, 0.f, 0.f, 0.f);
}

__global__ void zero_pool_kernel() {
    int i = blockIdx.x * blockDim.x + threadIdx.x;
    if (i < G_GRAPHS * H) g_pool[i] = 0.f;
    if (i < G_GRAPHS)     g_cnt[i]  = 0.f;
}

// shifted softplus: log(1+exp(v)) - log(2), numerically stable
__device__ __forceinline__ float ssp(float v) {
    return fmaxf(v, 0.f) + log1pf(expf(-fabsf(v))) - 0.69314718056f;
}

__device__ __forceinline__ unsigned f2tf32(float x) {
    unsigned u;
    asm("cvt.rna.tf32.f32 %0, %1;" : "=r"(u) : "f"(x));
    return u;
}

// ---------------- filter table build ----------------
__global__ void table_kernel(const float* __restrict__ Wf1, const float* __restrict__ bf1,
                             const float* __restrict__ Wf2, const float* __restrict__ bf2) {
    const int ROWS = 32;
    const int chunks = TAB / ROWS;
    int l  = blockIdx.x / chunks;
    int k0 = (blockIdx.x % chunks) * ROWS;
    int j  = threadIdx.x;                       // 128 threads

    __shared__ float rbf[H];
    __shared__ float hid[H];

    const float* w1 = Wf1 + (size_t)l * H * H;
    const float* w2 = Wf2 + (size_t)l * H * H;
    float b1v = bf1[l * H + j];
    float b2v = bf2[l * H + j];
    float cj  = j * (1.0f / (H - 1));

    for (int r = 0; r < ROWS; r++) {
        int k = k0 + r;
        float d = k * (1.0f / (TAB - 1));
        float u = d - cj;
        rbf[j] = expf(-GAMMA_C * u * u);
        __syncthreads();

        float acc = b1v;
        #pragma unroll 8
        for (int i = 0; i < H; i++) acc = fmaf(rbf[i], w1[(size_t)i * H + j], acc);
        float sp = ssp(acc);
        __syncthreads();
        hid[j] = sp;
        __syncthreads();

        float acc2 = b2v;
        #pragma unroll 8
        for (int i = 0; i < H; i++) acc2 = fmaf(hid[i], w2[(size_t)i * H + j], acc2);
        g_table[((size_t)l * TAB + k) * H + j] = __float2half_rn(acc2);
        __syncthreads();
    }
}

// ---------------- pipelined tf32 tensor-core GEMM ----------------
// C[M,128] = A[M,KDIM] @ B[KDIM,128] + bias (optional relu), OutT in {float,__half}
// CTA tile 128x128, 256 threads = 8 warps (2m x 4n), warp tile 64x32.
// B staged fully (tf32-converted once); A double-buffered via cp.async.
#define BM 128
#define AS_STRIDE 36
#define BS_STRIDE 132

__device__ __forceinline__ void cp_async16(unsigned saddr, const void* gaddr, int szbytes) {
    asm volatile("cp.async.cg.shared.global [%0], [%1], 16, %2;"
                 :: "r"(saddr), "l"(gaddr), "r"(szbytes));
}

template <int KDIM, bool RELU, typename OutT>
__global__ void __launch_bounds__(256, 2) gemm_tf32(const float* __restrict__ A,
                                                    const float* __restrict__ B,
                                                    const float* __restrict__ bias,
                                                    OutT* __restrict__ C, int M) {
    constexpr int KITERS = KDIM / 32;
    extern __shared__ float smem[];
    float* Bs = smem;                         // [KDIM][BS_STRIDE] tf32 bit patterns
    float* As = smem + KDIM * BS_STRIDE;      // [2][128][AS_STRIDE] raw f32

    int tid  = threadIdx.x;
    int lane = tid & 31;
    int wid  = tid >> 5;
    int wm   = wid >> 2;          // 0..1
    int wn   = wid & 3;           // 0..3
    int grp  = lane >> 2;         // 0..7
    int thr4 = lane & 3;          // 0..3
    int r0   = blockIdx.x * BM;

    // ---- issue A chunk staging via cp.async ----
    auto stage_A = [&](int chunk, int buf) {
        float* dstbase = As + buf * (BM * AS_STRIDE);
        #pragma unroll
        for (int j = 0; j < 4; j++) {
            int idx = tid + j * 256;
            int row = idx >> 3;          // 0..127
            int k4  = idx & 7;           // 0..7
            int gr  = r0 + row;
            int grc = gr < M ? gr : 0;
            const float* gp = A + (size_t)grc * KDIM + chunk * 32 + k4 * 4;
            unsigned sa = (unsigned)__cvta_generic_to_shared(dstbase + row * AS_STRIDE + k4 * 4);
            cp_async16(sa, gp, (gr < M) ? 16 : 0);
        }
        asm volatile("cp.async.commit_group;");
    };

    stage_A(0, 0);
    if (KITERS > 1) stage_A(1, 1);

    // ---- stage full B with tf32 convert (once) ----
    #pragma unroll
    for (int i = tid; i < KDIM * 32; i += 256) {
        int k  = i >> 5;
        int n4 = i & 31;
        float4 v = *(const float4*)(B + (size_t)k * H + n4 * 4);
        float* d = Bs + k * BS_STRIDE + n4 * 4;
        d[0] = __uint_as_float(f2tf32(v.x));
        d[1] = __uint_as_float(f2tf32(v.y));
        d[2] = __uint_as_float(f2tf32(v.z));
        d[3] = __uint_as_float(f2tf32(v.w));
    }

    float c[4][4][4];
    #pragma unroll
    for (int i = 0; i < 4; i++)
        #pragma unroll
        for (int j = 0; j < 4; j++)
            #pragma unroll
            for (int r = 0; r < 4; r++) c[i][j][r] = 0.f;

    #pragma unroll
    for (int ki = 0; ki < KITERS; ki++) {
        if (ki == KITERS - 1) asm volatile("cp.async.wait_group 0;" ::: "memory");
        else                  asm volatile("cp.async.wait_group 1;" ::: "memory");
        __syncthreads();

        const float* Ab = As + (ki & 1) * (BM * AS_STRIDE);
        #pragma unroll
        for (int ks = 0; ks < 4; ks++) {
            unsigned a[4][4];
            #pragma unroll
            for (int am = 0; am < 4; am++) {
                const float* base = Ab + (size_t)(wm * 64 + am * 16 + grp) * AS_STRIDE + ks * 8 + thr4;
                a[am][0] = f2tf32(base[0]);
                a[am][1] = f2tf32(base[8 * AS_STRIDE]);
                a[am][2] = f2tf32(base[4]);
                a[am][3] = f2tf32(base[8 * AS_STRIDE + 4]);
            }
            unsigned b[4][2];
            #pragma unroll
            for (int an = 0; an < 4; an++) {
                const float* bb = Bs + (size_t)(ki * 32 + ks * 8 + thr4) * BS_STRIDE + wn * 32 + an * 8 + grp;
                b[an][0] = __float_as_uint(bb[0]);
                b[an][1] = __float_as_uint(bb[4 * BS_STRIDE]);
            }
            #pragma unroll
            for (int am = 0; am < 4; am++)
                #pragma unroll
                for (int an = 0; an < 4; an++) {
                    asm volatile(
                        "mma.sync.aligned.m16n8k8.row.col.f32.tf32.tf32.f32 "
                        "{%0,%1,%2,%3}, {%4,%5,%6,%7}, {%8,%9}, {%0,%1,%2,%3};"
                        : "+f"(c[am][an][0]), "+f"(c[am][an][1]),
                          "+f"(c[am][an][2]), "+f"(c[am][an][3])
                        : "r"(a[am][0]), "r"(a[am][1]), "r"(a[am][2]), "r"(a[am][3]),
                          "r"(b[an][0]), "r"(b[an][1]));
                }
        }

        if (ki + 2 < KITERS) {
            __syncthreads();                 // all warps done reading buf (ki&1)
            stage_A(ki + 2, ki & 1);
        }
    }

    // ---- epilogue ----
    #pragma unroll
    for (int an = 0; an < 4; an++) {
        int col = wn * 32 + an * 8 + 2 * thr4;
        float2 bv = *(const float2*)(bias + col);
        #pragma unroll
        for (int am = 0; am < 4; am++) {
            int row0 = r0 + wm * 64 + am * 16 + grp;
            float2 o0, o1;
            o0.x = c[am][an][0] + bv.x;  o0.y = c[am][an][1] + bv.y;
            o1.x = c[am][an][2] + bv.x;  o1.y = c[am][an][3] + bv.y;
            if (RELU) {
                o0.x = fmaxf(o0.x, 0.f); o0.y = fmaxf(o0.y, 0.f);
                o1.x = fmaxf(o1.x, 0.f); o1.y = fmaxf(o1.y, 0.f);
            }
            if constexpr (sizeof(OutT) == 2) {
                __half2* cp0 = (__half2*)((__half*)C + (size_t)row0 * H + col);
                __half2* cp1 = (__half2*)((__half*)C + (size_t)(row0 + 8) * H + col);
                if (row0 < M)     *cp0 = __floats2half2_rn(o0.x, o0.y);
                if (row0 + 8 < M) *cp1 = __floats2half2_rn(o1.x, o1.y);
            } else {
                if (row0 < M)     *(float2*)((float*)C + (size_t)row0 * H + col)       = o0;
                if (row0 + 8 < M) *(float2*)((float*)C + (size_t)(row0 + 8) * H + col) = o1;
            }
        }
    }
}

// ---------------- edge kernel: gather-gate-scatter, fp16 table + fp16 proj ----------------
__global__ void edge_kernel(const __half* __restrict__ table,  // [TAB][H] for this layer
                            const __half* __restrict__ proj,   // [N][H] fp16
                            const float* __restrict__ dist,
                            const int*   __restrict__ src,
                            const int*   __restrict__ dst,
                            float*       __restrict__ agg, int E) {
    int e = blockIdx.x * 8 + (threadIdx.x >> 5);
    if (e >= E) return;
    int lane = threadIdx.x & 31;

    float d = __ldg(dist + e);
    int  s  = __ldg(src + e);
    int  t  = __ldg(dst + e);

    float pos = d * (float)(TAB - 1);
    int k = (int)pos;
    if (k < 0) k = 0;
    if (k > TAB - 2) k = TAB - 2;
    float fr = pos - (float)k;

    const uint2* trow = (const uint2*)(table + (size_t)k * H) + lane;
    uint2 q0 = __ldg(trow);
    uint2 q1 = __ldg(trow + (H / 4));
    uint2 hp = __ldg((const uint2*)(proj + (size_t)s * H) + lane);

    float2 f0a = __half22float2(*(const __half2*)&q0.x);
    float2 f0b = __half22float2(*(const __half2*)&q0.y);
    float2 f1a = __half22float2(*(const __half2*)&q1.x);
    float2 f1b = __half22float2(*(const __half2*)&q1.y);
    float2 p01 = __half22float2(*(const __half2*)&hp.x);
    float2 p23 = __half22float2(*(const __half2*)&hp.y);

    float mx = (f0a.x + fr * (f1a.x - f0a.x)) * p01.x;
    float my = (f0a.y + fr * (f1a.y - f0a.y)) * p01.y;
    float mz = (f0b.x + fr * (f1b.x - f0b.x)) * p23.x;
    float mw = (f0b.y + fr * (f1b.y - f0b.y)) * p23.y;

    float* out = agg + (size_t)t * H + lane * 4;
    asm volatile("red.global.add.v4.f32 [%0], {%1,%2,%3,%4};"
                 :: "l"(out), "f"(mx), "f"(my), "f"(mz), "f"(mw) : "memory");
}

// ---------------- graph pooling (sum + count) ----------------
__global__ void pool_kernel(const float* __restrict__ cur, const int* __restrict__ gid, int N) {
    int n = blockIdx.x * 8 + (threadIdx.x >> 5);
    if (n >= N) return;
    int lane = threadIdx.x & 31;
    int g = __ldg(gid + n);
    float4 v = __ldg((const float4*)(cur + (size_t)n * H) + lane);
    float* p = g_pool + (size_t)g * H + lane * 4;
    asm volatile("red.global.add.v4.f32 [%0], {%1,%2,%3,%4};"
                 :: "l"(p), "f"(v.x), "f"(v.y), "f"(v.z), "f"(v.w) : "memory");
    if (lane == 0) atomicAdd(&g_cnt[g], 1.0f);
}

// ---------------- readout: mean, FC, log_softmax ----------------
__global__ void readout_kernel(const float* __restrict__ fcw, const float* __restrict__ fcb,
                               float* __restrict__ out) {
    int g = blockIdx.x;
    int t = threadIdx.x;    // 128
    __shared__ float p[H];
    __shared__ float logits[C_OUT];

    float c = fmaxf(g_cnt[g], 1.0f);
    p[t] = g_pool[(size_t)g * H + t] / c;
    __syncthreads();

    if (t < C_OUT) {
        float acc = fcb[t];
        #pragma unroll 8
        for (int h = 0; h < H; h++) acc = fmaf(p[h], fcw[h * C_OUT + t], acc);
        logits[t] = acc;
    }
    __syncthreads();

    if (t == 0) {
        float mx = -1e30f;
        for (int i = 0; i < C_OUT; i++) mx = fmaxf(mx, logits[i]);
        float se = 0.f;
        for (int i = 0; i < C_OUT; i++) se += expf(logits[i] - mx);
        float lse = mx + logf(se);
        for (int i = 0; i < C_OUT; i++) out[g * C_OUT + i] = logits[i] - lse;
    }
}

// ---------------- launch ----------------
extern "C" void kernel_launch(void* const* d_in, const int* in_sizes, int n_in,
                              void* d_out, int out_size) {
    const float* x         = (const float*)d_in[0];
    const float* edge_dist = (const float*)d_in[1];
    const int*   esrc      = (const int*)  d_in[2];
    const int*   edst      = (const int*)  d_in[3];
    const int*   gid       = (const int*)  d_in[4];
    const float* W1_0      = (const float*)d_in[5];
    const float* b1_0      = (const float*)d_in[6];
    const float* W1_rest   = (const float*)d_in[7];
    const float* b1_rest   = (const float*)d_in[8];
    const float* Wf1       = (const float*)d_in[9];
    const float* bf1       = (const float*)d_in[10];
    const float* Wf2       = (const float*)d_in[11];
    const float* bf2       = (const float*)d_in[12];
    const float* W2        = (const float*)d_in[13];
    const float* b2        = (const float*)d_in[14];
    const float* fcw       = (const float*)d_in[15];
    const float* fcb       = (const float*)d_in[16];
    float* out = (float*)d_out;

    int E = in_sizes[1];
    int N = in_sizes[4];

    float *agg, *cur;
    __half *proj, *table;
    cudaGetSymbolAddress((void**)&proj,  g_proj);
    cudaGetSymbolAddress((void**)&agg,   g_agg);
    cudaGetSymbolAddress((void**)&cur,   g_cur);
    cudaGetSymbolAddress((void**)&table, g_table);

    // dynamic smem sizes & opt-in (idempotent host calls; not stream ops)
    const int smem128 = (128 * BS_STRIDE + 2 * BM * AS_STRIDE) * 4;
    const int smem64  = (64  * BS_STRIDE + 2 * BM * AS_STRIDE) * 4;
    cudaFuncSetAttribute(gemm_tf32<F_IN, false, __half>,
                         cudaFuncAttributeMaxDynamicSharedMemorySize, smem64);
    cudaFuncSetAttribute(gemm_tf32<H, false, __half>,
                         cudaFuncAttributeMaxDynamicSharedMemorySize, smem128);
    cudaFuncSetAttribute(gemm_tf32<H, true, float>,
                         cudaFuncAttributeMaxDynamicSharedMemorySize, smem128);

    // build per-layer filter tables (fp16, 4 MB, L2-resident)
    table_kernel<<<L_LAYERS * (TAB / 32), H>>>(Wf1, bf1, Wf2, bf2);

    int gemm_blocks = (N + BM - 1) / BM;
    int nh4 = (N * H) / 4;
    int zero_blocks = (nh4 + 255) / 256;
    int edge_blocks = (E + 7) / 8;

    for (int l = 0; l < L_LAYERS; l++) {
        // node projection (tf32 tensor cores, fp16 output)
        if (l == 0)
            gemm_tf32<F_IN, false, __half><<<gemm_blocks, 256, smem64>>>(x, W1_0, b1_0, proj, N);
        else
            gemm_tf32<H, false, __half><<<gemm_blocks, 256, smem128>>>(
                cur, W1_rest + (size_t)(l - 1) * H * H, b1_rest + (size_t)(l - 1) * H, proj, N);

        // zero accumulator
        zero4_kernel<<<zero_blocks, 256>>>((float4*)agg, nh4);

        // gather-gate-scatter over edges
        edge_kernel<<<edge_blocks, 256>>>(table + (size_t)l * TAB * H,
                                          proj, edge_dist, esrc, edst, agg, E);

        // output projection + relu (tf32 tensor cores, f32 output)
        gemm_tf32<H, true, float><<<gemm_blocks, 256, smem128>>>(
            agg, W2 + (size_t)l * H * H, b2 + (size_t)l * H, cur, N);
    }

    // graph mean pooling + FC + log_softmax
    zero_pool_kernel<<<(G_GRAPHS * H + 255) / 256, 256>>>();
    pool_kernel<<<(N + 7) / 8, 256>>>(cur, gid, N);
    readout_kernel<<<G_GRAPHS, H>>>(fcw, fcb, out);
}

// round 4
// speedup vs baseline: 1.9610x; 1.1435x over previous
#include <cuda_runtime.h>
#include <cuda_fp16.h>

// Problem constants (fixed by the reference)
#define N_NODES 50000
#define N_EDGES 800000
#define F_IN    64
#define H       128
#define L_LAYERS 4
#define G_GRAPHS 64
#define C_OUT   10
#define TAB     4096          // filter-table grid points per layer
#define GAMMA_C 10.0f

// ---------------- scratch (device globals: allocation-free) ----------------
__device__ __half g_proj[N_NODES * H];           // fp16 projected nodes (edge-gather source)
__device__ float  g_agg [N_NODES * H];
__device__ float  g_cur [N_NODES * H];
__device__ __half g_table[L_LAYERS * TAB * H];   // fp16 filter table (4 MB)
__device__ float  g_pool[G_GRAPHS * H];
__device__ float  g_cnt [G_GRAPHS];

// ---------------- small helpers ----------------
__global__ void zero4_kernel(float4* __restrict__ p, int n4) {
    int i = blockIdx.x * blockDim.x + threadIdx.x;
    if (i < n4) p[i] = make_float4(0.f, 0.f, 0.f, 0.f);
}

__global__ void zero_pool_kernel() {
    int i = blockIdx.x * blockDim.x + threadIdx.x;
    if (i < G_GRAPHS * H) g_pool[i] = 0.f;
    if (i < G_GRAPHS)     g_cnt[i]  = 0.f;
}

// shifted softplus: log(1+exp(v)) - log(2), numerically stable
__device__ __forceinline__ float ssp(float v) {
    return fmaxf(v, 0.f) + log1pf(expf(-fabsf(v))) - 0.6931472f;
}

__device__ __forceinline__ unsigned f2tf32(float x) {
    unsigned u;
    asm("cvt.rna.tf32.f32 %0, %1;" : "=r"(u) : "f"(x));
    return u;
}

__device__ __forceinline__ void cp_async16(unsigned saddr, const void* gaddr, int szbytes) {
    asm volatile("cp.async.cg.shared.global [%0], [%1], 16, %2;"
                 :: "r"(saddr), "l"(gaddr), "r"(szbytes));
}

// ---------------- filter table build ----------------
__global__ void table_kernel(const float* __restrict__ Wf1, const float* __restrict__ bf1,
                             const float* __restrict__ Wf2, const float* __restrict__ bf2) {
    const int ROWS = 32;
    const int chunks = TAB / ROWS;
    int l  = blockIdx.x / chunks;
    int k0 = (blockIdx.x % chunks) * ROWS;
    int j  = threadIdx.x;                       // 128 threads

    __shared__ float rbf[H];
    __shared__ float hid[H];

    const float* w1 = Wf1 + (size_t)l * H * H;
    const float* w2 = Wf2 + (size_t)l * H * H;
    float b1v = bf1[l * H + j];
    float b2v = bf2[l * H + j];
    float cj  = j * (1.0f / (H - 1));

    for (int r = 0; r < ROWS; r++) {
        int k = k0 + r;
        float d = k * (1.0f / (TAB - 1));
        float u = d - cj;
        rbf[j] = expf(-GAMMA_C * u * u);
        __syncthreads();

        float acc = b1v;
        #pragma unroll 8
        for (int i = 0; i < H; i++) acc = fmaf(rbf[i], w1[(size_t)i * H + j], acc);
        float sp = ssp(acc);
        __syncthreads();
        hid[j] = sp;
        __syncthreads();

        float acc2 = b2v;
        #pragma unroll 8
        for (int i = 0; i < H; i++) acc2 = fmaf(hid[i], w2[(size_t)i * H + j], acc2);
        g_table[((size_t)l * TAB + k) * H + j] = __float2half_rn(acc2);
        __syncthreads();
    }
}

// ---------------- GEMM tiling constants ----------------
#define BM 128
#define AS_STRIDE 36
#define BS_STRIDE 132
#define TS_STRIDE 136    // halves

// ---------------- pipelined tf32 tensor-core GEMM ----------------
template <int KDIM, bool RELU, typename OutT>
__global__ void __launch_bounds__(256, 2) gemm_tf32(const float* __restrict__ A,
                                                    const float* __restrict__ B,
                                                    const float* __restrict__ bias,
                                                    OutT* __restrict__ C, int M) {
    constexpr int KITERS = KDIM / 32;
    extern __shared__ float smem[];
    float* Bs = smem;                         // [KDIM][BS_STRIDE] tf32 bit patterns
    float* As = smem + KDIM * BS_STRIDE;      // [2][128][AS_STRIDE] raw f32

    int tid  = threadIdx.x;
    int lane = tid & 31;
    int wid  = tid >> 5;
    int wm   = wid >> 2;
    int wn   = wid & 3;
    int grp  = lane >> 2;
    int thr4 = lane & 3;
    int r0   = blockIdx.x * BM;

    auto stage_A = [&](int chunk, int buf) {
        float* dstbase = As + buf * (BM * AS_STRIDE);
        #pragma unroll
        for (int j = 0; j < 4; j++) {
            int idx = tid + j * 256;
            int row = idx >> 3;
            int k4  = idx & 7;
            int gr  = r0 + row;
            int grc = gr < M ? gr : 0;
            const float* gp = A + (size_t)grc * KDIM + chunk * 32 + k4 * 4;
            unsigned sa = (unsigned)__cvta_generic_to_shared(dstbase + row * AS_STRIDE + k4 * 4);
            cp_async16(sa, gp, (gr < M) ? 16 : 0);
        }
        asm volatile("cp.async.commit_group;");
    };

    stage_A(0, 0);
    if (KITERS > 1) stage_A(1, 1);

    #pragma unroll
    for (int i = tid; i < KDIM * 32; i += 256) {
        int k  = i >> 5;
        int n4 = i & 31;
        float4 v = *(const float4*)(B + (size_t)k * H + n4 * 4);
        float* d = Bs + k * BS_STRIDE + n4 * 4;
        d[0] = __uint_as_float(f2tf32(v.x));
        d[1] = __uint_as_float(f2tf32(v.y));
        d[2] = __uint_as_float(f2tf32(v.z));
        d[3] = __uint_as_float(f2tf32(v.w));
    }

    float c[4][4][4];
    #pragma unroll
    for (int i = 0; i < 4; i++)
        #pragma unroll
        for (int j = 0; j < 4; j++)
            #pragma unroll
            for (int r = 0; r < 4; r++) c[i][j][r] = 0.f;

    #pragma unroll
    for (int ki = 0; ki < KITERS; ki++) {
        if (ki == KITERS - 1) asm volatile("cp.async.wait_group 0;" ::: "memory");
        else                  asm volatile("cp.async.wait_group 1;" ::: "memory");
        __syncthreads();

        const float* Ab = As + (ki & 1) * (BM * AS_STRIDE);
        #pragma unroll
        for (int ks = 0; ks < 4; ks++) {
            unsigned a[4][4];
            #pragma unroll
            for (int am = 0; am < 4; am++) {
                const float* base = Ab + (size_t)(wm * 64 + am * 16 + grp) * AS_STRIDE + ks * 8 + thr4;
                a[am][0] = f2tf32(base[0]);
                a[am][1] = f2tf32(base[8 * AS_STRIDE]);
                a[am][2] = f2tf32(base[4]);
                a[am][3] = f2tf32(base[8 * AS_STRIDE + 4]);
            }
            unsigned b[4][2];
            #pragma unroll
            for (int an = 0; an < 4; an++) {
                const float* bb = Bs + (size_t)(ki * 32 + ks * 8 + thr4) * BS_STRIDE + wn * 32 + an * 8 + grp;
                b[an][0] = __float_as_uint(bb[0]);
                b[an][1] = __float_as_uint(bb[4 * BS_STRIDE]);
            }
            #pragma unroll
            for (int am = 0; am < 4; am++)
                #pragma unroll
                for (int an = 0; an < 4; an++) {
                    asm volatile(
                        "mma.sync.aligned.m16n8k8.row.col.f32.tf32.tf32.f32 "
                        "{%0,%1,%2,%3}, {%4,%5,%6,%7}, {%8,%9}, {%0,%1,%2,%3};"
                        : "+f"(c[am][an][0]), "+f"(c[am][an][1]),
                          "+f"(c[am][an][2]), "+f"(c[am][an][3])
                        : "r"(a[am][0]), "r"(a[am][1]), "r"(a[am][2]), "r"(a[am][3]),
                          "r"(b[an][0]), "r"(b[an][1]));
                }
        }

        if (ki + 2 < KITERS) {
            __syncthreads();
            stage_A(ki + 2, ki & 1);
        }
    }

    #pragma unroll
    for (int an = 0; an < 4; an++) {
        int col = wn * 32 + an * 8 + 2 * thr4;
        float2 bv = *(const float2*)(bias + col);
        #pragma unroll
        for (int am = 0; am < 4; am++) {
            int row0 = r0 + wm * 64 + am * 16 + grp;
            float2 o0, o1;
            o0.x = c[am][an][0] + bv.x;  o0.y = c[am][an][1] + bv.y;
            o1.x = c[am][an][2] + bv.x;  o1.y = c[am][an][3] + bv.y;
            if (RELU) {
                o0.x = fmaxf(o0.x, 0.f); o0.y = fmaxf(o0.y, 0.f);
                o1.x = fmaxf(o1.x, 0.f); o1.y = fmaxf(o1.y, 0.f);
            }
            if constexpr (sizeof(OutT) == 2) {
                __half2* cp0 = (__half2*)((__half*)C + (size_t)row0 * H + col);
                __half2* cp1 = (__half2*)((__half*)C + (size_t)(row0 + 8) * H + col);
                if (row0 < M)     *cp0 = __floats2half2_rn(o0.x, o0.y);
                if (row0 + 8 < M) *cp1 = __floats2half2_rn(o1.x, o1.y);
            } else {
                if (row0 < M)     *(float2*)((float*)C + (size_t)row0 * H + col)       = o0;
                if (row0 + 8 < M) *(float2*)((float*)C + (size_t)(row0 + 8) * H + col) = o1;
            }
        }
    }
}

// ---------------- fused dual GEMM: P = relu(A@W2 + b2) @ W1 + b1 (fp16 out) ----------------
// First GEMM tf32 (A f32 via cp.async, W2 tf32 smem); intermediate T -> smem fp16;
// second GEMM fp16 (mma.m16n8k16) with W1^T staged fp16 in smem.
__global__ void __launch_bounds__(256, 1) fused_gemm(const float* __restrict__ A,
                                                     const float* __restrict__ W2,
                                                     const float* __restrict__ b2,
                                                     const float* __restrict__ W1,
                                                     const float* __restrict__ b1,
                                                     __half* __restrict__ P, int M) {
    extern __shared__ float smem[];
    float*  Bs = smem;                               // [128][132] tf32 (W2)
    float*  As = smem + 128 * BS_STRIDE;             // [2][128][36] f32
    __half* Ts = (__half*)(As + 2 * BM * AS_STRIDE); // [128][136] fp16 intermediate
    __half* Bt = Ts + 128 * TS_STRIDE;               // [128][136] fp16 W1^T ([n][k])

    int tid  = threadIdx.x;
    int lane = tid & 31;
    int wid  = tid >> 5;
    int wm   = wid >> 2;
    int wn   = wid & 3;
    int grp  = lane >> 2;
    int thr4 = lane & 3;
    int r0   = blockIdx.x * BM;

    auto stage_A = [&](int chunk, int buf) {
        float* dstbase = As + buf * (BM * AS_STRIDE);
        #pragma unroll
        for (int j = 0; j < 4; j++) {
            int idx = tid + j * 256;
            int row = idx >> 3;
            int k4  = idx & 7;
            int gr  = r0 + row;
            int grc = gr < M ? gr : 0;
            const float* gp = A + (size_t)grc * H + chunk * 32 + k4 * 4;
            unsigned sa = (unsigned)__cvta_generic_to_shared(dstbase + row * AS_STRIDE + k4 * 4);
            cp_async16(sa, gp, (gr < M) ? 16 : 0);
        }
        asm volatile("cp.async.commit_group;");
    };

    stage_A(0, 0);
    stage_A(1, 1);

    // stage W2 as tf32 [k][n]
    #pragma unroll
    for (int i = tid; i < 128 * 32; i += 256) {
        int k  = i >> 5;
        int n4 = i & 31;
        float4 v = *(const float4*)(W2 + (size_t)k * H + n4 * 4);
        float* d = Bs + k * BS_STRIDE + n4 * 4;
        d[0] = __uint_as_float(f2tf32(v.x));
        d[1] = __uint_as_float(f2tf32(v.y));
        d[2] = __uint_as_float(f2tf32(v.z));
        d[3] = __uint_as_float(f2tf32(v.w));
    }
    // stage W1 transposed as fp16: Bt[n][k] = W1[k][n]
    #pragma unroll
    for (int i = tid; i < 128 * 64; i += 256) {
        int k  = i >> 6;
        int n2 = (i & 63) * 2;
        float2 v = *(const float2*)(W1 + (size_t)k * H + n2);
        Bt[(size_t)n2 * TS_STRIDE + k]       = __float2half_rn(v.x);
        Bt[(size_t)(n2 + 1) * TS_STRIDE + k] = __float2half_rn(v.y);
    }

    float c[4][4][4];
    #pragma unroll
    for (int i = 0; i < 4; i++)
        #pragma unroll
        for (int j = 0; j < 4; j++)
            #pragma unroll
            for (int r = 0; r < 4; r++) c[i][j][r] = 0.f;

    // ---- first GEMM: A @ W2 (tf32), K=128 ----
    #pragma unroll
    for (int ki = 0; ki < 4; ki++) {
        if (ki == 3) asm volatile("cp.async.wait_group 0;" ::: "memory");
        else         asm volatile("cp.async.wait_group 1;" ::: "memory");
        __syncthreads();

        const float* Ab = As + (ki & 1) * (BM * AS_STRIDE);
        #pragma unroll
        for (int ks = 0; ks < 4; ks++) {
            unsigned a[4][4];
            #pragma unroll
            for (int am = 0; am < 4; am++) {
                const float* base = Ab + (size_t)(wm * 64 + am * 16 + grp) * AS_STRIDE + ks * 8 + thr4;
                a[am][0] = f2tf32(base[0]);
                a[am][1] = f2tf32(base[8 * AS_STRIDE]);
                a[am][2] = f2tf32(base[4]);
                a[am][3] = f2tf32(base[8 * AS_STRIDE + 4]);
            }
            unsigned b[4][2];
            #pragma unroll
            for (int an = 0; an < 4; an++) {
                const float* bb = Bs + (size_t)(ki * 32 + ks * 8 + thr4) * BS_STRIDE + wn * 32 + an * 8 + grp;
                b[an][0] = __float_as_uint(bb[0]);
                b[an][1] = __float_as_uint(bb[4 * BS_STRIDE]);
            }
            #pragma unroll
            for (int am = 0; am < 4; am++)
                #pragma unroll
                for (int an = 0; an < 4; an++) {
                    asm volatile(
                        "mma.sync.aligned.m16n8k8.row.col.f32.tf32.tf32.f32 "
                        "{%0,%1,%2,%3}, {%4,%5,%6,%7}, {%8,%9}, {%0,%1,%2,%3};"
                        : "+f"(c[am][an][0]), "+f"(c[am][an][1]),
                          "+f"(c[am][an][2]), "+f"(c[am][an][3])
                        : "r"(a[am][0]), "r"(a[am][1]), "r"(a[am][2]), "r"(a[am][3]),
                          "r"(b[an][0]), "r"(b[an][1]));
                }
        }
        if (ki + 2 < 4) {
            __syncthreads();
            stage_A(ki + 2, ki & 1);
        }
    }

    // ---- bias + relu -> Ts (fp16 [m][k]) ----
    #pragma unroll
    for (int an = 0; an < 4; an++) {
        int col = wn * 32 + an * 8 + 2 * thr4;
        float2 bv = *(const float2*)(b2 + col);
        #pragma unroll
        for (int am = 0; am < 4; am++) {
            int r = wm * 64 + am * 16 + grp;
            float2 o0, o1;
            o0.x = fmaxf(c[am][an][0] + bv.x, 0.f);
            o0.y = fmaxf(c[am][an][1] + bv.y, 0.f);
            o1.x = fmaxf(c[am][an][2] + bv.x, 0.f);
            o1.y = fmaxf(c[am][an][3] + bv.y, 0.f);
            *(__half2*)(Ts + (size_t)r * TS_STRIDE + col)       = __floats2half2_rn(o0.x, o0.y);
            *(__half2*)(Ts + (size_t)(r + 8) * TS_STRIDE + col) = __floats2half2_rn(o1.x, o1.y);
        }
    }
    __syncthreads();

    // ---- second GEMM: T @ W1 (fp16, m16n8k16), K=128 ----
    float p[4][4][4];
    #pragma unroll
    for (int i = 0; i < 4; i++)
        #pragma unroll
        for (int j = 0; j < 4; j++)
            #pragma unroll
            for (int r = 0; r < 4; r++) p[i][j][r] = 0.f;

    #pragma unroll
    for (int kc = 0; kc < 8; kc++) {
        unsigned a[4][4];
        #pragma unroll
        for (int am = 0; am < 4; am++) {
            const __half* tb = Ts + (size_t)(wm * 64 + am * 16 + grp) * TS_STRIDE + kc * 16 + 2 * thr4;
            a[am][0] = *(const unsigned*)tb;
            a[am][1] = *(const unsigned*)(tb + 8 * TS_STRIDE);
            a[am][2] = *(const unsigned*)(tb + 8);
            a[am][3] = *(const unsigned*)(tb + 8 * TS_STRIDE + 8);
        }
        unsigned b[4][2];
        #pragma unroll
        for (int an = 0; an < 4; an++) {
            const __half* bb = Bt + (size_t)(wn * 32 + an * 8 + grp) * TS_STRIDE + kc * 16 + 2 * thr4;
            b[an][0] = *(const unsigned*)bb;
            b[an][1] = *(const unsigned*)(bb + 8);
        }
        #pragma unroll
        for (int am = 0; am < 4; am++)
            #pragma unroll
            for (int an = 0; an < 4; an++) {
                asm volatile(
                    "mma.sync.aligned.m16n8k16.row.col.f32.f16.f16.f32 "
                    "{%0,%1,%2,%3}, {%4,%5,%6,%7}, {%8,%9}, {%0,%1,%2,%3};"
                    : "+f"(p[am][an][0]), "+f"(p[am][an][1]),
                      "+f"(p[am][an][2]), "+f"(p[am][an][3])
                    : "r"(a[am][0]), "r"(a[am][1]), "r"(a[am][2]), "r"(a[am][3]),
                      "r"(b[an][0]), "r"(b[an][1]));
            }
    }

    // ---- epilogue: + b1, store fp16 proj ----
    #pragma unroll
    for (int an = 0; an < 4; an++) {
        int col = wn * 32 + an * 8 + 2 * thr4;
        float2 bv = *(const float2*)(b1 + col);
        #pragma unroll
        for (int am = 0; am < 4; am++) {
            int row0 = r0 + wm * 64 + am * 16 + grp;
            if (row0 < M)
                *(__half2*)(P + (size_t)row0 * H + col) =
                    __floats2half2_rn(p[am][an][0] + bv.x, p[am][an][1] + bv.y);
            if (row0 + 8 < M)
                *(__half2*)(P + (size_t)(row0 + 8) * H + col) =
                    __floats2half2_rn(p[am][an][2] + bv.x, p[am][an][3] + bv.y);
        }
    }
}

// ---------------- edge kernel: 4 edges per warp (ILP), fp16 table lerp + fp16 proj ----------------
__global__ void edge_kernel(const __half* __restrict__ table,
                            const __half* __restrict__ proj,
                            const float* __restrict__ dist,
                            const int*   __restrict__ src,
                            const int*   __restrict__ dst,
                            float*       __restrict__ agg, int E) {
    int warp = blockIdx.x * 8 + (threadIdx.x >> 5);
    int lane = threadIdx.x & 31;
    int e0 = warp * 4;
    if (e0 >= E) return;

    float d[4]; int s[4], t[4]; bool v[4];
    #pragma unroll
    for (int i = 0; i < 4; i++) {
        int e = e0 + i;
        v[i] = e < E;
        int ec = v[i] ? e : e0;
        d[i] = __ldg(dist + ec);
        s[i] = __ldg(src + ec);
        t[i] = __ldg(dst + ec);
    }

    uint2 q0[4], q1[4], hp[4];
    float fr[4];
    #pragma unroll
    for (int i = 0; i < 4; i++) {
        float pos = d[i] * (float)(TAB - 1);
        int k = (int)pos;
        k = min(max(k, 0), TAB - 2);
        fr[i] = pos - (float)k;
        const uint2* trow = (const uint2*)(table + (size_t)k * H) + lane;
        q0[i] = __ldg(trow);
        q1[i] = __ldg(trow + (H / 4));
        hp[i] = __ldg((const uint2*)(proj + (size_t)s[i] * H) + lane);
    }

    #pragma unroll
    for (int i = 0; i < 4; i++) {
        float2 f0a = __half22float2(*(const __half2*)&q0[i].x);
        float2 f0b = __half22float2(*(const __half2*)&q0[i].y);
        float2 f1a = __half22float2(*(const __half2*)&q1[i].x);
        float2 f1b = __half22float2(*(const __half2*)&q1[i].y);
        float2 p01 = __half22float2(*(const __half2*)&hp[i].x);
        float2 p23 = __half22float2(*(const __half2*)&hp[i].y);

        float mx = (f0a.x + fr[i] * (f1a.x - f0a.x)) * p01.x;
        float my = (f0a.y + fr[i] * (f1a.y - f0a.y)) * p01.y;
        float mz = (f0b.x + fr[i] * (f1b.x - f0b.x)) * p23.x;
        float mw = (f0b.y + fr[i] * (f1b.y - f0b.y)) * p23.y;

        if (v[i]) {
            float* out = agg + (size_t)t[i] * H + lane * 4;
            asm volatile("red.global.add.v4.f32 [%0], {%1,%2,%3,%4};"
                         :: "l"(out), "f"(mx), "f"(my), "f"(mz), "f"(mw) : "memory");
        }
    }
}

// ---------------- graph pooling (sum + count) ----------------
__global__ void pool_kernel(const float* __restrict__ cur, const int* __restrict__ gid, int N) {
    int n = blockIdx.x * 8 + (threadIdx.x >> 5);
    if (n >= N) return;
    int lane = threadIdx.x & 31;
    int g = __ldg(gid + n);
    float4 v = __ldg((const float4*)(cur + (size_t)n * H) + lane);
    float* p = g_pool + (size_t)g * H + lane * 4;
    asm volatile("red.global.add.v4.f32 [%0], {%1,%2,%3,%4};"
                 :: "l"(p), "f"(v.x), "f"(v.y), "f"(v.z), "f"(v.w) : "memory");
    if (lane == 0) atomicAdd(&g_cnt[g], 1.0f);
}

// ---------------- readout: mean, FC, log_softmax ----------------
__global__ void readout_kernel(const float* __restrict__ fcw, const float* __restrict__ fcb,
                               float* __restrict__ out) {
    int g = blockIdx.x;
    int t = threadIdx.x;    // 128
    __shared__ float p[H];
    __shared__ float logits[C_OUT];

    float c = fmaxf(g_cnt[g], 1.0f);
    p[t] = g_pool[(size_t)g * H + t] / c;
    __syncthreads();

    if (t < C_OUT) {
        float acc = fcb[t];
        #pragma unroll 8
        for (int h = 0; h < H; h++) acc = fmaf(p[h], fcw[h * C_OUT + t], acc);
        logits[t] = acc;
    }
    __syncthreads();

    if (t == 0) {
        float mx = -1e30f;
        for (int i = 0; i < C_OUT; i++) mx = fmaxf(mx, logits[i]);
        float se = 0.f;
        for (int i = 0; i < C_OUT; i++) se += expf(logits[i] - mx);
        float lse = mx + logf(se);
        for (int i = 0; i < C_OUT; i++) out[g * C_OUT + i] = logits[i] - lse;
    }
}

// ---------------- launch ----------------
extern "C" void kernel_launch(void* const* d_in, const int* in_sizes, int n_in,
                              void* d_out, int out_size) {
    const float* x         = (const float*)d_in[0];
    const float* edge_dist = (const float*)d_in[1];
    const int*   esrc      = (const int*)  d_in[2];
    const int*   edst      = (const int*)  d_in[3];
    const int*   gid       = (const int*)  d_in[4];
    const float* W1_0      = (const float*)d_in[5];
    const float* b1_0      = (const float*)d_in[6];
    const float* W1_rest   = (const float*)d_in[7];
    const float* b1_rest   = (const float*)d_in[8];
    const float* Wf1       = (const float*)d_in[9];
    const float* bf1       = (const float*)d_in[10];
    const float* Wf2       = (const float*)d_in[11];
    const float* bf2       = (const float*)d_in[12];
    const float* W2        = (const float*)d_in[13];
    const float* b2        = (const float*)d_in[14];
    const float* fcw       = (const float*)d_in[15];
    const float* fcb       = (const float*)d_in[16];
    float* out = (float*)d_out;

    int E = in_sizes[1];
    int N = in_sizes[4];

    float *agg, *cur;
    __half *proj, *table;
    cudaGetSymbolAddress((void**)&proj,  g_proj);
    cudaGetSymbolAddress((void**)&agg,   g_agg);
    cudaGetSymbolAddress((void**)&cur,   g_cur);
    cudaGetSymbolAddress((void**)&table, g_table);

    const int smem128  = (128 * BS_STRIDE + 2 * BM * AS_STRIDE) * 4;
    const int smem64   = (64  * BS_STRIDE + 2 * BM * AS_STRIDE) * 4;
    const int smemFuse = (128 * BS_STRIDE + 2 * BM * AS_STRIDE) * 4 + 2 * (128 * TS_STRIDE) * 2;
    cudaFuncSetAttribute(gemm_tf32<F_IN, false, __half>,
                         cudaFuncAttributeMaxDynamicSharedMemorySize, smem64);
    cudaFuncSetAttribute(gemm_tf32<H, true, float>,
                         cudaFuncAttributeMaxDynamicSharedMemorySize, smem128);
    cudaFuncSetAttribute(fused_gemm,
                         cudaFuncAttributeMaxDynamicSharedMemorySize, smemFuse);

    // build per-layer filter tables (fp16, 4 MB, L2-resident)
    table_kernel<<<L_LAYERS * (TAB / 32), H>>>(Wf1, bf1, Wf2, bf2);

    int gemm_blocks = (N + BM - 1) / BM;
    int nh4 = (N * H) / 4;
    int zero_blocks = (nh4 + 255) / 256;
    int edge_blocks = (E + 31) / 32;

    // initial projection: proj = x @ W1_0 + b1_0 (fp16 out)
    gemm_tf32<F_IN, false, __half><<<gemm_blocks, 256, smem64>>>(x, W1_0, b1_0, proj, N);

    for (int l = 0; l < L_LAYERS; l++) {
        zero4_kernel<<<zero_blocks, 256>>>((float4*)agg, nh4);

        edge_kernel<<<edge_blocks, 256>>>(table + (size_t)l * TAB * H,
                                          proj, edge_dist, esrc, edst, agg, E);

        if (l < L_LAYERS - 1) {
            // proj_{l+1} = relu(agg @ W2_l + b2_l) @ W1_{l+1} + b1_{l+1}
            fused_gemm<<<gemm_blocks, 256, smemFuse>>>(
                agg,
                W2 + (size_t)l * H * H, b2 + (size_t)l * H,
                W1_rest + (size_t)l * H * H, b1_rest + (size_t)l * H,
                proj, N);
        } else {
            // final: cur = relu(agg @ W2_3 + b2_3)
            gemm_tf32<H, true, float><<<gemm_blocks, 256, smem128>>>(
                agg, W2 + (size_t)l * H * H, b2 + (size_t)l * H, cur, N);
        }
    }

    // graph mean pooling + FC + log_softmax
    zero_pool_kernel<<<(G_GRAPHS * H + 255) / 256, 256>>>();
    pool_kernel<<<(N + 7) / 8, 256>>>(cur, gid, N);
    readout_kernel<<<G_GRAPHS, H>>>(fcw, fcb, out);
}

// round 5
// speedup vs baseline: 3.6475x; 1.8600x over previous
#include <cuda_runtime.h>
#include <cuda_fp16.h>

// Problem constants (fixed by the reference)
#define N_NODES 50000
#define N_EDGES 800000
#define F_IN    64
#define H       128
#define L_LAYERS 4
#define G_GRAPHS 64
#define C_OUT   10
#define TAB     1024          // filter-table grid points per layer
#define GAMMA_C 10.0f

// ---------------- scratch (device globals: allocation-free) ----------------
__device__ __half g_proj[N_NODES * H];           // fp16 projected nodes (edge-gather source)
__device__ float  g_agg [N_NODES * H];
__device__ __half g_cur [N_NODES * H];
__device__ __half g_table[L_LAYERS * TAB * H];   // fp16 filter table (1 MB)
__device__ float  g_pool[G_GRAPHS * H];
__device__ float  g_cnt [G_GRAPHS];
// CSR-by-dst scratch
__device__ int    g_deg   [N_NODES];
__device__ int    g_rowptr[N_NODES + 1];
__device__ int    g_cursor[N_NODES];
__device__ int    g_bsum  [64];
__device__ int    g_boff  [64];
__device__ int    g_src_s [N_EDGES];
__device__ float  g_dist_s[N_EDGES];

// ---------------- small helpers ----------------
__global__ void zero_pool_kernel() {
    int i = blockIdx.x * blockDim.x + threadIdx.x;
    if (i < G_GRAPHS * H) g_pool[i] = 0.f;
    if (i < G_GRAPHS)     g_cnt[i]  = 0.f;
}

__device__ __forceinline__ float ssp(float v) {
    return fmaxf(v, 0.f) + log1pf(expf(-fabsf(v))) - 0.6931472f;
}

__device__ __forceinline__ unsigned f2tf32(float x) {
    unsigned u;
    asm("cvt.rna.tf32.f32 %0, %1;" : "=r"(u) : "f"(x));
    return u;
}

__device__ __forceinline__ void cp_async16(unsigned saddr, const void* gaddr, int szbytes) {
    asm volatile("cp.async.cg.shared.global [%0], [%1], 16, %2;"
                 :: "r"(saddr), "l"(gaddr), "r"(szbytes));
}

// ---------------- CSR build ----------------
__global__ void deg_zero_kernel(int N) {
    int i = blockIdx.x * blockDim.x + threadIdx.x;
    if (i < N) g_deg[i] = 0;
}

__global__ void deg_count_kernel(const int* __restrict__ dst, int E) {
    int e = blockIdx.x * blockDim.x + threadIdx.x;
    if (e < E) atomicAdd(&g_deg[dst[e]], 1);
}

__global__ void scan_bsum_kernel(int N) {
    __shared__ int sh[1024];
    int t = threadIdx.x;
    int i = blockIdx.x * 1024 + t;
    sh[t] = (i < N) ? g_deg[i] : 0;
    __syncthreads();
    for (int ofs = 512; ofs > 0; ofs >>= 1) {
        if (t < ofs) sh[t] += sh[t + ofs];
        __syncthreads();
    }
    if (t == 0) g_bsum[blockIdx.x] = sh[0];
}

__global__ void scan_boff_kernel(int nb, int E) {
    __shared__ int sh[64];
    int t = threadIdx.x;   // 64 threads
    int v = (t < nb) ? g_bsum[t] : 0;
    sh[t] = v;
    __syncthreads();
    #pragma unroll
    for (int ofs = 1; ofs < 64; ofs <<= 1) {
        int x = (t >= ofs) ? sh[t - ofs] : 0;
        __syncthreads();
        sh[t] += x;
        __syncthreads();
    }
    if (t < nb) g_boff[t] = sh[t] - v;     // exclusive
    if (t == 0) g_rowptr[N_NODES] = E;
}

__global__ void scan_final_kernel(int N) {
    __shared__ int sh[1024];
    int t = threadIdx.x;
    int i = blockIdx.x * 1024 + t;
    int v = (i < N) ? g_deg[i] : 0;
    sh[t] = v;
    __syncthreads();
    for (int ofs = 1; ofs < 1024; ofs <<= 1) {
        int x = (t >= ofs) ? sh[t - ofs] : 0;
        __syncthreads();
        sh[t] += x;
        __syncthreads();
    }
    if (i < N) {
        int ex = sh[t] - v + g_boff[blockIdx.x];
        g_rowptr[i] = ex;
        g_cursor[i] = ex;
    }
}

__global__ void scatter_kernel(const int* __restrict__ src, const int* __restrict__ dst,
                               const float* __restrict__ dist, int E) {
    int e = blockIdx.x * blockDim.x + threadIdx.x;
    if (e < E) {
        int p = atomicAdd(&g_cursor[dst[e]], 1);
        g_src_s[p]  = src[e];
        g_dist_s[p] = dist[e];
    }
}

// ---------------- filter table build (weights staged in smem) ----------------
// table[l][k][j] = ( ssp( rbf(d_k) @ Wf1_l + bf1_l ) @ Wf2_l + bf2_l )[j]
#define TROWS 16
__global__ void table_kernel(const float* __restrict__ Wf1, const float* __restrict__ bf1,
                             const float* __restrict__ Wf2, const float* __restrict__ bf2) {
    extern __shared__ float ts[];
    float* wbuf = ts;                   // [H][H]
    float* rbfb = ts + H * H;           // [TROWS][H]
    float* hidb = rbfb + TROWS * H;     // [TROWS][H]

    const int chunks = TAB / TROWS;
    int l  = blockIdx.x / chunks;
    int r0 = (blockIdx.x % chunks) * TROWS;
    int j  = threadIdx.x;               // 128 threads
    float cj = j * (1.0f / (H - 1));

    #pragma unroll
    for (int r = 0; r < TROWS; r++) {
        float d = (r0 + r) * (1.0f / (TAB - 1));
        float u = d - cj;
        rbfb[r * H + j] = expf(-GAMMA_C * u * u);
    }

    const float4* w1 = (const float4*)(Wf1 + (size_t)l * H * H);
    for (int i = j; i < H * H / 4; i += 128) ((float4*)wbuf)[i] = __ldg(w1 + i);
    __syncthreads();

    float b1v = bf1[l * H + j];
    float b2v = bf2[l * H + j];

    #pragma unroll 2
    for (int r = 0; r < TROWS; r++) {
        float acc = b1v;
        #pragma unroll 8
        for (int i = 0; i < H; i++) acc = fmaf(rbfb[r * H + i], wbuf[i * H + j], acc);
        hidb[r * H + j] = ssp(acc);
    }
    __syncthreads();

    const float4* w2 = (const float4*)(Wf2 + (size_t)l * H * H);
    for (int i = j; i < H * H / 4; i += 128) ((float4*)wbuf)[i] = __ldg(w2 + i);
    __syncthreads();

    #pragma unroll 2
    for (int r = 0; r < TROWS; r++) {
        float acc = b2v;
        #pragma unroll 8
        for (int i = 0; i < H; i++) acc = fmaf(hidb[r * H + i], wbuf[i * H + j], acc);
        g_table[((size_t)l * TAB + r0 + r) * H + j] = __float2half_rn(acc);
    }
}

// ---------------- GEMM tiling constants ----------------
#define BM 128
#define AS_STRIDE 36
#define BS_STRIDE 132
#define TS_STRIDE 136    // halves

// ---------------- pipelined tf32 tensor-core GEMM ----------------
template <int KDIM, bool RELU, typename OutT>
__global__ void __launch_bounds__(256, 2) gemm_tf32(const float* __restrict__ A,
                                                    const float* __restrict__ B,
                                                    const float* __restrict__ bias,
                                                    OutT* __restrict__ C, int M) {
    constexpr int KITERS = KDIM / 32;
    extern __shared__ float smem[];
    float* Bs = smem;
    float* As = smem + KDIM * BS_STRIDE;

    int tid  = threadIdx.x;
    int lane = tid & 31;
    int wid  = tid >> 5;
    int wm   = wid >> 2;
    int wn   = wid & 3;
    int grp  = lane >> 2;
    int thr4 = lane & 3;
    int r0   = blockIdx.x * BM;

    auto stage_A = [&](int chunk, int buf) {
        float* dstbase = As + buf * (BM * AS_STRIDE);
        #pragma unroll
        for (int j = 0; j < 4; j++) {
            int idx = tid + j * 256;
            int row = idx >> 3;
            int k4  = idx & 7;
            int gr  = r0 + row;
            int grc = gr < M ? gr : 0;
            const float* gp = A + (size_t)grc * KDIM + chunk * 32 + k4 * 4;
            unsigned sa = (unsigned)__cvta_generic_to_shared(dstbase + row * AS_STRIDE + k4 * 4);
            cp_async16(sa, gp, (gr < M) ? 16 : 0);
        }
        asm volatile("cp.async.commit_group;");
    };

    stage_A(0, 0);
    if (KITERS > 1) stage_A(1, 1);

    #pragma unroll
    for (int i = tid; i < KDIM * 32; i += 256) {
        int k  = i >> 5;
        int n4 = i & 31;
        float4 v = *(const float4*)(B + (size_t)k * H + n4 * 4);
        float* d = Bs + k * BS_STRIDE + n4 * 4;
        d[0] = __uint_as_float(f2tf32(v.x));
        d[1] = __uint_as_float(f2tf32(v.y));
        d[2] = __uint_as_float(f2tf32(v.z));
        d[3] = __uint_as_float(f2tf32(v.w));
    }

    float c[4][4][4];
    #pragma unroll
    for (int i = 0; i < 4; i++)
        #pragma unroll
        for (int j = 0; j < 4; j++)
            #pragma unroll
            for (int r = 0; r < 4; r++) c[i][j][r] = 0.f;

    #pragma unroll
    for (int ki = 0; ki < KITERS; ki++) {
        if (ki == KITERS - 1) asm volatile("cp.async.wait_group 0;" ::: "memory");
        else                  asm volatile("cp.async.wait_group 1;" ::: "memory");
        __syncthreads();

        const float* Ab = As + (ki & 1) * (BM * AS_STRIDE);
        #pragma unroll
        for (int ks = 0; ks < 4; ks++) {
            unsigned a[4][4];
            #pragma unroll
            for (int am = 0; am < 4; am++) {
                const float* base = Ab + (size_t)(wm * 64 + am * 16 + grp) * AS_STRIDE + ks * 8 + thr4;
                a[am][0] = f2tf32(base[0]);
                a[am][1] = f2tf32(base[8 * AS_STRIDE]);
                a[am][2] = f2tf32(base[4]);
                a[am][3] = f2tf32(base[8 * AS_STRIDE + 4]);
            }
            unsigned b[4][2];
            #pragma unroll
            for (int an = 0; an < 4; an++) {
                const float* bb = Bs + (size_t)(ki * 32 + ks * 8 + thr4) * BS_STRIDE + wn * 32 + an * 8 + grp;
                b[an][0] = __float_as_uint(bb[0]);
                b[an][1] = __float_as_uint(bb[4 * BS_STRIDE]);
            }
            #pragma unroll
            for (int am = 0; am < 4; am++)
                #pragma unroll
                for (int an = 0; an < 4; an++) {
                    asm volatile(
                        "mma.sync.aligned.m16n8k8.row.col.f32.tf32.tf32.f32 "
                        "{%0,%1,%2,%3}, {%4,%5,%6,%7}, {%8,%9}, {%0,%1,%2,%3};"
                        : "+f"(c[am][an][0]), "+f"(c[am][an][1]),
                          "+f"(c[am][an][2]), "+f"(c[am][an][3])
                        : "r"(a[am][0]), "r"(a[am][1]), "r"(a[am][2]), "r"(a[am][3]),
                          "r"(b[an][0]), "r"(b[an][1]));
                }
        }

        if (ki + 2 < KITERS) {
            __syncthreads();
            stage_A(ki + 2, ki & 1);
        }
    }

    #pragma unroll
    for (int an = 0; an < 4; an++) {
        int col = wn * 32 + an * 8 + 2 * thr4;
        float2 bv = *(const float2*)(bias + col);
        #pragma unroll
        for (int am = 0; am < 4; am++) {
            int row0 = r0 + wm * 64 + am * 16 + grp;
            float2 o0, o1;
            o0.x = c[am][an][0] + bv.x;  o0.y = c[am][an][1] + bv.y;
            o1.x = c[am][an][2] + bv.x;  o1.y = c[am][an][3] + bv.y;
            if (RELU) {
                o0.x = fmaxf(o0.x, 0.f); o0.y = fmaxf(o0.y, 0.f);
                o1.x = fmaxf(o1.x, 0.f); o1.y = fmaxf(o1.y, 0.f);
            }
            if constexpr (sizeof(OutT) == 2) {
                __half2* cp0 = (__half2*)((__half*)C + (size_t)row0 * H + col);
                __half2* cp1 = (__half2*)((__half*)C + (size_t)(row0 + 8) * H + col);
                if (row0 < M)     *cp0 = __floats2half2_rn(o0.x, o0.y);
                if (row0 + 8 < M) *cp1 = __floats2half2_rn(o1.x, o1.y);
            } else {
                if (row0 < M)     *(float2*)((float*)C + (size_t)row0 * H + col)       = o0;
                if (row0 + 8 < M) *(float2*)((float*)C + (size_t)(row0 + 8) * H + col) = o1;
            }
        }
    }
}

// ---------------- fused dual GEMM: P = relu(A@W2 + b2) @ W1 + b1 (fp16 out) ----------------
__global__ void __launch_bounds__(256, 1) fused_gemm(const float* __restrict__ A,
                                                     const float* __restrict__ W2,
                                                     const float* __restrict__ b2,
                                                     const float* __restrict__ W1,
                                                     const float* __restrict__ b1,
                                                     __half* __restrict__ P, int M) {
    extern __shared__ float smem[];
    float*  Bs = smem;
    float*  As = smem + 128 * BS_STRIDE;
    __half* Ts = (__half*)(As + 2 * BM * AS_STRIDE);
    __half* Bt = Ts + 128 * TS_STRIDE;

    int tid  = threadIdx.x;
    int lane = tid & 31;
    int wid  = tid >> 5;
    int wm   = wid >> 2;
    int wn   = wid & 3;
    int grp  = lane >> 2;
    int thr4 = lane & 3;
    int r0   = blockIdx.x * BM;

    auto stage_A = [&](int chunk, int buf) {
        float* dstbase = As + buf * (BM * AS_STRIDE);
        #pragma unroll
        for (int j = 0; j < 4; j++) {
            int idx = tid + j * 256;
            int row = idx >> 3;
            int k4  = idx & 7;
            int gr  = r0 + row;
            int grc = gr < M ? gr : 0;
            const float* gp = A + (size_t)grc * H + chunk * 32 + k4 * 4;
            unsigned sa = (unsigned)__cvta_generic_to_shared(dstbase + row * AS_STRIDE + k4 * 4);
            cp_async16(sa, gp, (gr < M) ? 16 : 0);
        }
        asm volatile("cp.async.commit_group;");
    };

    stage_A(0, 0);
    stage_A(1, 1);

    #pragma unroll
    for (int i = tid; i < 128 * 32; i += 256) {
        int k  = i >> 5;
        int n4 = i & 31;
        float4 v = *(const float4*)(W2 + (size_t)k * H + n4 * 4);
        float* d = Bs + k * BS_STRIDE + n4 * 4;
        d[0] = __uint_as_float(f2tf32(v.x));
        d[1] = __uint_as_float(f2tf32(v.y));
        d[2] = __uint_as_float(f2tf32(v.z));
        d[3] = __uint_as_float(f2tf32(v.w));
    }
    #pragma unroll
    for (int i = tid; i < 128 * 64; i += 256) {
        int k  = i >> 6;
        int n2 = (i & 63) * 2;
        float2 v = *(const float2*)(W1 + (size_t)k * H + n2);
        Bt[(size_t)n2 * TS_STRIDE + k]       = __float2half_rn(v.x);
        Bt[(size_t)(n2 + 1) * TS_STRIDE + k] = __float2half_rn(v.y);
    }

    float c[4][4][4];
    #pragma unroll
    for (int i = 0; i < 4; i++)
        #pragma unroll
        for (int j = 0; j < 4; j++)
            #pragma unroll
            for (int r = 0; r < 4; r++) c[i][j][r] = 0.f;

    #pragma unroll
    for (int ki = 0; ki < 4; ki++) {
        if (ki == 3) asm volatile("cp.async.wait_group 0;" ::: "memory");
        else         asm volatile("cp.async.wait_group 1;" ::: "memory");
        __syncthreads();

        const float* Ab = As + (ki & 1) * (BM * AS_STRIDE);
        #pragma unroll
        for (int ks = 0; ks < 4; ks++) {
            unsigned a[4][4];
            #pragma unroll
            for (int am = 0; am < 4; am++) {
                const float* base = Ab + (size_t)(wm * 64 + am * 16 + grp) * AS_STRIDE + ks * 8 + thr4;
                a[am][0] = f2tf32(base[0]);
                a[am][1] = f2tf32(base[8 * AS_STRIDE]);
                a[am][2] = f2tf32(base[4]);
                a[am][3] = f2tf32(base[8 * AS_STRIDE + 4]);
            }
            unsigned b[4][2];
            #pragma unroll
            for (int an = 0; an < 4; an++) {
                const float* bb = Bs + (size_t)(ki * 32 + ks * 8 + thr4) * BS_STRIDE + wn * 32 + an * 8 + grp;
                b[an][0] = __float_as_uint(bb[0]);
                b[an][1] = __float_as_uint(bb[4 * BS_STRIDE]);
            }
            #pragma unroll
            for (int am = 0; am < 4; am++)
                #pragma unroll
                for (int an = 0; an < 4; an++) {
                    asm volatile(
                        "mma.sync.aligned.m16n8k8.row.col.f32.tf32.tf32.f32 "
                        "{%0,%1,%2,%3}, {%4,%5,%6,%7}, {%8,%9}, {%0,%1,%2,%3};"
                        : "+f"(c[am][an][0]), "+f"(c[am][an][1]),
                          "+f"(c[am][an][2]), "+f"(c[am][an][3])
                        : "r"(a[am][0]), "r"(a[am][1]), "r"(a[am][2]), "r"(a[am][3]),
                          "r"(b[an][0]), "r"(b[an][1]));
                }
        }
        if (ki + 2 < 4) {
            __syncthreads();
            stage_A(ki + 2, ki & 1);
        }
    }

    #pragma unroll
    for (int an = 0; an < 4; an++) {
        int col = wn * 32 + an * 8 + 2 * thr4;
        float2 bv = *(const float2*)(b2 + col);
        #pragma unroll
        for (int am = 0; am < 4; am++) {
            int r = wm * 64 + am * 16 + grp;
            float2 o0, o1;
            o0.x = fmaxf(c[am][an][0] + bv.x, 0.f);
            o0.y = fmaxf(c[am][an][1] + bv.y, 0.f);
            o1.x = fmaxf(c[am][an][2] + bv.x, 0.f);
            o1.y = fmaxf(c[am][an][3] + bv.y, 0.f);
            *(__half2*)(Ts + (size_t)r * TS_STRIDE + col)       = __floats2half2_rn(o0.x, o0.y);
            *(__half2*)(Ts + (size_t)(r + 8) * TS_STRIDE + col) = __floats2half2_rn(o1.x, o1.y);
        }
    }
    __syncthreads();

    float p[4][4][4];
    #pragma unroll
    for (int i = 0; i < 4; i++)
        #pragma unroll
        for (int j = 0; j < 4; j++)
            #pragma unroll
            for (int r = 0; r < 4; r++) p[i][j][r] = 0.f;

    #pragma unroll
    for (int kc = 0; kc < 8; kc++) {
        unsigned a[4][4];
        #pragma unroll
        for (int am = 0; am < 4; am++) {
            const __half* tb = Ts + (size_t)(wm * 64 + am * 16 + grp) * TS_STRIDE + kc * 16 + 2 * thr4;
            a[am][0] = *(const unsigned*)tb;
            a[am][1] = *(const unsigned*)(tb + 8 * TS_STRIDE);
            a[am][2] = *(const unsigned*)(tb + 8);
            a[am][3] = *(const unsigned*)(tb + 8 * TS_STRIDE + 8);
        }
        unsigned b[4][2];
        #pragma unroll
        for (int an = 0; an < 4; an++) {
            const __half* bb = Bt + (size_t)(wn * 32 + an * 8 + grp) * TS_STRIDE + kc * 16 + 2 * thr4;
            b[an][0] = *(const unsigned*)bb;
            b[an][1] = *(const unsigned*)(bb + 8);
        }
        #pragma unroll
        for (int am = 0; am < 4; am++)
            #pragma unroll
            for (int an = 0; an < 4; an++) {
                asm volatile(
                    "mma.sync.aligned.m16n8k16.row.col.f32.f16.f16.f32 "
                    "{%0,%1,%2,%3}, {%4,%5,%6,%7}, {%8,%9}, {%0,%1,%2,%3};"
                    : "+f"(p[am][an][0]), "+f"(p[am][an][1]),
                      "+f"(p[am][an][2]), "+f"(p[am][an][3])
                    : "r"(a[am][0]), "r"(a[am][1]), "r"(a[am][2]), "r"(a[am][3]),
                      "r"(b[an][0]), "r"(b[an][1]));
            }
    }

    #pragma unroll
    for (int an = 0; an < 4; an++) {
        int col = wn * 32 + an * 8 + 2 * thr4;
        float2 bv = *(const float2*)(b1 + col);
        #pragma unroll
        for (int am = 0; am < 4; am++) {
            int row0 = r0 + wm * 64 + am * 16 + grp;
            if (row0 < M)
                *(__half2*)(P + (size_t)row0 * H + col) =
                    __floats2half2_rn(p[am][an][0] + bv.x, p[am][an][1] + bv.y);
            if (row0 + 8 < M)
                *(__half2*)(P + (size_t)(row0 + 8) * H + col) =
                    __floats2half2_rn(p[am][an][2] + bv.x, p[am][an][3] + bv.y);
        }
    }
}

// ---------------- CSR aggregation: warp per dst node, register accumulator ----------------
__global__ void agg_kernel(const __half* __restrict__ table,
                           const __half* __restrict__ proj,
                           const int*   __restrict__ rowptr,
                           const int*   __restrict__ srcs,
                           const float* __restrict__ dists,
                           float*       __restrict__ agg, int N) {
    int n = blockIdx.x * 8 + (threadIdx.x >> 5);
    if (n >= N) return;
    int lane = threadIdx.x & 31;

    int beg = __ldg(rowptr + n);
    int end = __ldg(rowptr + n + 1);

    float ax = 0.f, ay = 0.f, az = 0.f, aw = 0.f;

    int s_n = 0, k_n = 0;
    float fr_n = 0.f;
    if (beg < end) {
        s_n = __ldg(srcs + beg);
        float d = __ldg(dists + beg);
        float pos = d * (float)(TAB - 1);
        int kk = (int)pos;
        kk = min(max(kk, 0), TAB - 2);
        fr_n = pos - (float)kk;
        k_n = kk;
    }

    for (int i = beg; i < end; i++) {
        int s = s_n, k = k_n;
        float fr = fr_n;
        if (i + 1 < end) {
            s_n = __ldg(srcs + i + 1);
            float d = __ldg(dists + i + 1);
            float pos = d * (float)(TAB - 1);
            int kk = (int)pos;
            kk = min(max(kk, 0), TAB - 2);
            fr_n = pos - (float)kk;
            k_n = kk;
        }

        const uint2* trow = (const uint2*)(table + (size_t)k * H) + lane;
        uint2 q0 = __ldg(trow);
        uint2 q1 = __ldg(trow + (H / 4));
        uint2 hp = __ldg((const uint2*)(proj + (size_t)s * H) + lane);

        float2 f0a = __half22float2(*(const __half2*)&q0.x);
        float2 f0b = __half22float2(*(const __half2*)&q0.y);
        float2 f1a = __half22float2(*(const __half2*)&q1.x);
        float2 f1b = __half22float2(*(const __half2*)&q1.y);
        float2 p01 = __half22float2(*(const __half2*)&hp.x);
        float2 p23 = __half22float2(*(const __half2*)&hp.y);

        ax = fmaf((f0a.x + fr * (f1a.x - f0a.x)), p01.x, ax);
        ay = fmaf((f0a.y + fr * (f1a.y - f0a.y)), p01.y, ay);
        az = fmaf((f0b.x + fr * (f1b.x - f0b.x)), p23.x, az);
        aw = fmaf((f0b.y + fr * (f1b.y - f0b.y)), p23.y, aw);
    }

    float4 o;
    o.x = ax; o.y = ay; o.z = az; o.w = aw;
    *(float4*)(agg + (size_t)n * H + lane * 4) = o;
}

// ---------------- graph pooling (sum + count), fp16 input ----------------
__global__ void pool_kernel(const __half* __restrict__ cur, const int* __restrict__ gid, int N) {
    int n = blockIdx.x * 8 + (threadIdx.x >> 5);
    if (n >= N) return;
    int lane = threadIdx.x & 31;
    int g = __ldg(gid + n);
    uint2 hv = __ldg((const uint2*)(cur + (size_t)n * H) + lane);
    float2 v01 = __half22float2(*(const __half2*)&hv.x);
    float2 v23 = __half22float2(*(const __half2*)&hv.y);
    float* p = g_pool + (size_t)g * H + lane * 4;
    asm volatile("red.global.add.v4.f32 [%0], {%1,%2,%3,%4};"
                 :: "l"(p), "f"(v01.x), "f"(v01.y), "f"(v23.x), "f"(v23.y) : "memory");
    if (lane == 0) atomicAdd(&g_cnt[g], 1.0f);
}

// ---------------- readout: mean, FC, log_softmax ----------------
__global__ void readout_kernel(const float* __restrict__ fcw, const float* __restrict__ fcb,
                               float* __restrict__ out) {
    int g = blockIdx.x;
    int t = threadIdx.x;    // 128
    __shared__ float p[H];
    __shared__ float logits[C_OUT];

    float c = fmaxf(g_cnt[g], 1.0f);
    p[t] = g_pool[(size_t)g * H + t] / c;
    __syncthreads();

    if (t < C_OUT) {
        float acc = fcb[t];
        #pragma unroll 8
        for (int h = 0; h < H; h++) acc = fmaf(p[h], fcw[h * C_OUT + t], acc);
        logits[t] = acc;
    }
    __syncthreads();

    if (t == 0) {
        float mx = -1e30f;
        for (int i = 0; i < C_OUT; i++) mx = fmaxf(mx, logits[i]);
        float se = 0.f;
        for (int i = 0; i < C_OUT; i++) se += expf(logits[i] - mx);
        float lse = mx + logf(se);
        for (int i = 0; i < C_OUT; i++) out[g * C_OUT + i] = logits[i] - lse;
    }
}

// ---------------- launch ----------------
extern "C" void kernel_launch(void* const* d_in, const int* in_sizes, int n_in,
                              void* d_out, int out_size) {
    const float* x         = (const float*)d_in[0];
    const float* edge_dist = (const float*)d_in[1];
    const int*   esrc      = (const int*)  d_in[2];
    const int*   edst      = (const int*)  d_in[3];
    const int*   gid       = (const int*)  d_in[4];
    const float* W1_0      = (const float*)d_in[5];
    const float* b1_0      = (const float*)d_in[6];
    const float* W1_rest   = (const float*)d_in[7];
    const float* b1_rest   = (const float*)d_in[8];
    const float* Wf1       = (const float*)d_in[9];
    const float* bf1       = (const float*)d_in[10];
    const float* Wf2       = (const float*)d_in[11];
    const float* bf2       = (const float*)d_in[12];
    const float* W2        = (const float*)d_in[13];
    const float* b2        = (const float*)d_in[14];
    const float* fcw       = (const float*)d_in[15];
    const float* fcb       = (const float*)d_in[16];
    float* out = (float*)d_out;

    int E = in_sizes[1];
    int N = in_sizes[4];

    float *agg;
    __half *proj, *table, *cur;
    int *rowptr, *src_s;
    float *dist_s;
    cudaGetSymbolAddress((void**)&proj,   g_proj);
    cudaGetSymbolAddress((void**)&agg,    g_agg);
    cudaGetSymbolAddress((void**)&cur,    g_cur);
    cudaGetSymbolAddress((void**)&table,  g_table);
    cudaGetSymbolAddress((void**)&rowptr, g_rowptr);
    cudaGetSymbolAddress((void**)&src_s,  g_src_s);
    cudaGetSymbolAddress((void**)&dist_s, g_dist_s);

    const int smem128  = (128 * BS_STRIDE + 2 * BM * AS_STRIDE) * 4;
    const int smem64   = (64  * BS_STRIDE + 2 * BM * AS_STRIDE) * 4;
    const int smemFuse = (128 * BS_STRIDE + 2 * BM * AS_STRIDE) * 4 + 2 * (128 * TS_STRIDE) * 2;
    const int smemTab  = (H * H + 2 * TROWS * H) * 4;
    cudaFuncSetAttribute(gemm_tf32<F_IN, false, __half>,
                         cudaFuncAttributeMaxDynamicSharedMemorySize, smem64);
    cudaFuncSetAttribute(gemm_tf32<H, true, __half>,
                         cudaFuncAttributeMaxDynamicSharedMemorySize, smem128);
    cudaFuncSetAttribute(fused_gemm,
                         cudaFuncAttributeMaxDynamicSharedMemorySize, smemFuse);
    cudaFuncSetAttribute(table_kernel,
                         cudaFuncAttributeMaxDynamicSharedMemorySize, smemTab);

    // build per-layer filter tables
    table_kernel<<<L_LAYERS * (TAB / TROWS), H, smemTab>>>(Wf1, bf1, Wf2, bf2);

    // build CSR by dst (inside the graph, deterministic work each call)
    int nb = (N + 1023) / 1024;
    deg_zero_kernel<<<(N + 255) / 256, 256>>>(N);
    deg_count_kernel<<<(E + 255) / 256, 256>>>(edst, E);
    scan_bsum_kernel<<<nb, 1024>>>(N);
    scan_boff_kernel<<<1, 64>>>(nb, E);
    scan_final_kernel<<<nb, 1024>>>(N);
    scatter_kernel<<<(E + 255) / 256, 256>>>(esrc, edst, edge_dist, E);

    int gemm_blocks = (N + BM - 1) / BM;
    int agg_blocks  = (N + 7) / 8;

    // initial projection: proj = x @ W1_0 + b1_0 (fp16 out)
    gemm_tf32<F_IN, false, __half><<<gemm_blocks, 256, smem64>>>(x, W1_0, b1_0, proj, N);

    for (int l = 0; l < L_LAYERS; l++) {
        agg_kernel<<<agg_blocks, 256>>>(table + (size_t)l * TAB * H,
                                        proj, rowptr, src_s, dist_s, agg, N);

        if (l < L_LAYERS - 1) {
            fused_gemm<<<gemm_blocks, 256, smemFuse>>>(
                agg,
                W2 + (size_t)l * H * H, b2 + (size_t)l * H,
                W1_rest + (size_t)l * H * H, b1_rest + (size_t)l * H,
                proj, N);
        } else {
            gemm_tf32<H, true, __half><<<gemm_blocks, 256, smem128>>>(
                agg, W2 + (size_t)l * H * H, b2 + (size_t)l * H, cur, N);
        }
    }

    // graph mean pooling + FC + log_softmax
    zero_pool_kernel<<<(G_GRAPHS * H + 255) / 256, 256>>>();
    pool_kernel<<<(N + 7) / 8, 256>>>(cur, gid, N);
    readout_kernel<<<G_GRAPHS, H>>>(fcw, fcb, out);
}

// round 6
// speedup vs baseline: 3.6536x; 1.0017x over previous
#include <cuda_runtime.h>
#include <cuda_fp16.h>

// Problem constants (fixed by the reference)
#define N_NODES 50000
#define N_EDGES 800000
#define F_IN    64
#define H       128
#define L_LAYERS 4
#define G_GRAPHS 64
#define C_OUT   10
#define TAB     1024
#define GAMMA_C 10.0f

// ---------------- scratch (device globals: allocation-free) ----------------
__device__ __half g_proj[N_NODES * H];
__device__ __half g_agg [N_NODES * H];
__device__ __half g_cur [N_NODES * H];
__device__ __half g_table[L_LAYERS * TAB * H];
__device__ float  g_pool[G_GRAPHS * H];
__device__ float  g_cnt [G_GRAPHS];
// CSR-by-dst scratch
__device__ int    g_deg   [N_NODES];
__device__ int    g_rowptr[N_NODES + 1];
__device__ int    g_cursor[N_NODES];
__device__ int    g_bsum  [64];
__device__ int    g_boff  [64];
__device__ int    g_src_s [N_EDGES];
__device__ float  g_dist_s[N_EDGES];

// ---------------- small helpers ----------------
__global__ void zero_pool_kernel() {
    int i = blockIdx.x * blockDim.x + threadIdx.x;
    if (i < G_GRAPHS * H) g_pool[i] = 0.f;
    if (i < G_GRAPHS)     g_cnt[i]  = 0.f;
}

__device__ __forceinline__ float ssp(float v) {
    return fmaxf(v, 0.f) + log1pf(expf(-fabsf(v))) - 0.6931472f;
}

__device__ __forceinline__ unsigned f2tf32(float x) {
    unsigned u;
    asm("cvt.rna.tf32.f32 %0, %1;" : "=r"(u) : "f"(x));
    return u;
}

__device__ __forceinline__ void cp_async16(unsigned saddr, const void* gaddr, int szbytes) {
    asm volatile("cp.async.cg.shared.global [%0], [%1], 16, %2;"
                 :: "r"(saddr), "l"(gaddr), "r"(szbytes));
}

// ---------------- CSR build ----------------
__global__ void deg_zero_kernel(int N) {
    int i = blockIdx.x * blockDim.x + threadIdx.x;
    if (i < N) g_deg[i] = 0;
}

__global__ void deg_count_kernel(const int* __restrict__ dst, int E) {
    int e = blockIdx.x * blockDim.x + threadIdx.x;
    if (e < E) atomicAdd(&g_deg[dst[e]], 1);
}

__global__ void scan_bsum_kernel(int N) {
    __shared__ int sh[1024];
    int t = threadIdx.x;
    int i = blockIdx.x * 1024 + t;
    sh[t] = (i < N) ? g_deg[i] : 0;
    __syncthreads();
    for (int ofs = 512; ofs > 0; ofs >>= 1) {
        if (t < ofs) sh[t] += sh[t + ofs];
        __syncthreads();
    }
    if (t == 0) g_bsum[blockIdx.x] = sh[0];
}

__global__ void scan_boff_kernel(int nb, int E) {
    __shared__ int sh[64];
    int t = threadIdx.x;   // 64 threads
    int v = (t < nb) ? g_bsum[t] : 0;
    sh[t] = v;
    __syncthreads();
    #pragma unroll
    for (int ofs = 1; ofs < 64; ofs <<= 1) {
        int x = (t >= ofs) ? sh[t - ofs] : 0;
        __syncthreads();
        sh[t] += x;
        __syncthreads();
    }
    if (t < nb) g_boff[t] = sh[t] - v;
    if (t == 0) g_rowptr[N_NODES] = E;
}

__global__ void scan_final_kernel(int N) {
    __shared__ int sh[1024];
    int t = threadIdx.x;
    int i = blockIdx.x * 1024 + t;
    int v = (i < N) ? g_deg[i] : 0;
    sh[t] = v;
    __syncthreads();
    for (int ofs = 1; ofs < 1024; ofs <<= 1) {
        int x = (t >= ofs) ? sh[t - ofs] : 0;
        __syncthreads();
        sh[t] += x;
        __syncthreads();
    }
    if (i < N) {
        int ex = sh[t] - v + g_boff[blockIdx.x];
        g_rowptr[i] = ex;
        g_cursor[i] = ex;
    }
}

__global__ void scatter_kernel(const int* __restrict__ src, const int* __restrict__ dst,
                               const float* __restrict__ dist, int E) {
    int e = blockIdx.x * blockDim.x + threadIdx.x;
    if (e < E) {
        int p = atomicAdd(&g_cursor[dst[e]], 1);
        g_src_s[p]  = src[e];
        g_dist_s[p] = dist[e];
    }
}

// ---------------- filter table build (weights staged in smem) ----------------
#define TROWS 16
__global__ void table_kernel(const float* __restrict__ Wf1, const float* __restrict__ bf1,
                             const float* __restrict__ Wf2, const float* __restrict__ bf2) {
    extern __shared__ float ts[];
    float* wbuf = ts;
    float* rbfb = ts + H * H;
    float* hidb = rbfb + TROWS * H;

    const int chunks = TAB / TROWS;
    int l  = blockIdx.x / chunks;
    int r0 = (blockIdx.x % chunks) * TROWS;
    int j  = threadIdx.x;
    float cj = j * (1.0f / (H - 1));

    #pragma unroll
    for (int r = 0; r < TROWS; r++) {
        float d = (r0 + r) * (1.0f / (TAB - 1));
        float u = d - cj;
        rbfb[r * H + j] = expf(-GAMMA_C * u * u);
    }

    const float4* w1 = (const float4*)(Wf1 + (size_t)l * H * H);
    for (int i = j; i < H * H / 4; i += 128) ((float4*)wbuf)[i] = __ldg(w1 + i);
    __syncthreads();

    float b1v = bf1[l * H + j];
    float b2v = bf2[l * H + j];

    #pragma unroll 2
    for (int r = 0; r < TROWS; r++) {
        float acc = b1v;
        #pragma unroll 8
        for (int i = 0; i < H; i++) acc = fmaf(rbfb[r * H + i], wbuf[i * H + j], acc);
        hidb[r * H + j] = ssp(acc);
    }
    __syncthreads();

    const float4* w2 = (const float4*)(Wf2 + (size_t)l * H * H);
    for (int i = j; i < H * H / 4; i += 128) ((float4*)wbuf)[i] = __ldg(w2 + i);
    __syncthreads();

    #pragma unroll 2
    for (int r = 0; r < TROWS; r++) {
        float acc = b2v;
        #pragma unroll 8
        for (int i = 0; i < H; i++) acc = fmaf(hidb[r * H + i], wbuf[i * H + j], acc);
        g_table[((size_t)l * TAB + r0 + r) * H + j] = __float2half_rn(acc);
    }
}

// ---------------- GEMM tiling constants ----------------
#define BM 128
#define AS_STRIDE 36
#define BS_STRIDE 132
#define TS_STRIDE 136    // halves

// ---------------- pipelined tf32 GEMM (initial projection only, K=64) ----------------
template <int KDIM>
__global__ void __launch_bounds__(256, 2) gemm_tf32(const float* __restrict__ A,
                                                    const float* __restrict__ B,
                                                    const float* __restrict__ bias,
                                                    __half* __restrict__ C, int M) {
    constexpr int KITERS = KDIM / 32;
    extern __shared__ float smem[];
    float* Bs = smem;
    float* As = smem + KDIM * BS_STRIDE;

    int tid  = threadIdx.x;
    int lane = tid & 31;
    int wid  = tid >> 5;
    int wm   = wid >> 2;
    int wn   = wid & 3;
    int grp  = lane >> 2;
    int thr4 = lane & 3;
    int r0   = blockIdx.x * BM;

    auto stage_A = [&](int chunk, int buf) {
        float* dstbase = As + buf * (BM * AS_STRIDE);
        #pragma unroll
        for (int j = 0; j < 4; j++) {
            int idx = tid + j * 256;
            int row = idx >> 3;
            int k4  = idx & 7;
            int gr  = r0 + row;
            int grc = gr < M ? gr : 0;
            const float* gp = A + (size_t)grc * KDIM + chunk * 32 + k4 * 4;
            unsigned sa = (unsigned)__cvta_generic_to_shared(dstbase + row * AS_STRIDE + k4 * 4);
            cp_async16(sa, gp, (gr < M) ? 16 : 0);
        }
        asm volatile("cp.async.commit_group;");
    };

    stage_A(0, 0);
    if (KITERS > 1) stage_A(1, 1);

    #pragma unroll
    for (int i = tid; i < KDIM * 32; i += 256) {
        int k  = i >> 5;
        int n4 = i & 31;
        float4 v = *(const float4*)(B + (size_t)k * H + n4 * 4);
        float* d = Bs + k * BS_STRIDE + n4 * 4;
        d[0] = __uint_as_float(f2tf32(v.x));
        d[1] = __uint_as_float(f2tf32(v.y));
        d[2] = __uint_as_float(f2tf32(v.z));
        d[3] = __uint_as_float(f2tf32(v.w));
    }

    float c[4][4][4];
    #pragma unroll
    for (int i = 0; i < 4; i++)
        #pragma unroll
        for (int j = 0; j < 4; j++)
            #pragma unroll
            for (int r = 0; r < 4; r++) c[i][j][r] = 0.f;

    #pragma unroll
    for (int ki = 0; ki < KITERS; ki++) {
        if (ki == KITERS - 1) asm volatile("cp.async.wait_group 0;" ::: "memory");
        else                  asm volatile("cp.async.wait_group 1;" ::: "memory");
        __syncthreads();

        const float* Ab = As + (ki & 1) * (BM * AS_STRIDE);
        #pragma unroll
        for (int ks = 0; ks < 4; ks++) {
            unsigned a[4][4];
            #pragma unroll
            for (int am = 0; am < 4; am++) {
                const float* base = Ab + (size_t)(wm * 64 + am * 16 + grp) * AS_STRIDE + ks * 8 + thr4;
                a[am][0] = f2tf32(base[0]);
                a[am][1] = f2tf32(base[8 * AS_STRIDE]);
                a[am][2] = f2tf32(base[4]);
                a[am][3] = f2tf32(base[8 * AS_STRIDE + 4]);
            }
            unsigned b[4][2];
            #pragma unroll
            for (int an = 0; an < 4; an++) {
                const float* bb = Bs + (size_t)(ki * 32 + ks * 8 + thr4) * BS_STRIDE + wn * 32 + an * 8 + grp;
                b[an][0] = __float_as_uint(bb[0]);
                b[an][1] = __float_as_uint(bb[4 * BS_STRIDE]);
            }
            #pragma unroll
            for (int am = 0; am < 4; am++)
                #pragma unroll
                for (int an = 0; an < 4; an++) {
                    asm volatile(
                        "mma.sync.aligned.m16n8k8.row.col.f32.tf32.tf32.f32 "
                        "{%0,%1,%2,%3}, {%4,%5,%6,%7}, {%8,%9}, {%0,%1,%2,%3};"
                        : "+f"(c[am][an][0]), "+f"(c[am][an][1]),
                          "+f"(c[am][an][2]), "+f"(c[am][an][3])
                        : "r"(a[am][0]), "r"(a[am][1]), "r"(a[am][2]), "r"(a[am][3]),
                          "r"(b[an][0]), "r"(b[an][1]));
                }
        }

        if (ki + 2 < KITERS) {
            __syncthreads();
            stage_A(ki + 2, ki & 1);
        }
    }

    #pragma unroll
    for (int an = 0; an < 4; an++) {
        int col = wn * 32 + an * 8 + 2 * thr4;
        float2 bv = *(const float2*)(bias + col);
        #pragma unroll
        for (int am = 0; am < 4; am++) {
            int row0 = r0 + wm * 64 + am * 16 + grp;
            if (row0 < M)
                *(__half2*)(C + (size_t)row0 * H + col) =
                    __floats2half2_rn(c[am][an][0] + bv.x, c[am][an][1] + bv.y);
            if (row0 + 8 < M)
                *(__half2*)(C + (size_t)(row0 + 8) * H + col) =
                    __floats2half2_rn(c[am][an][2] + bv.x, c[am][an][3] + bv.y);
        }
    }
}

// ---------------- fp16 layer GEMM ----------------
// !LAST: P = relu(A@W2 + b2) @ W1 + b1   (A fp16 in gmem, all-fp16 mma)
//  LAST: P = relu(A@W2 + b2)
template <bool LAST>
__global__ void __launch_bounds__(256, 2) layer_gemm(const __half* __restrict__ A,
                                                     const float* __restrict__ W2,
                                                     const float* __restrict__ b2,
                                                     const float* __restrict__ W1,
                                                     const float* __restrict__ b1,
                                                     __half* __restrict__ P, int M) {
    extern __shared__ __half shh[];
    __half* Ah  = shh;                        // [128][TS_STRIDE]  A, later Ts
    __half* W2t = shh + 128 * TS_STRIDE;      // [n][k]
    __half* W1t = W2t + 128 * TS_STRIDE;      // [n][k] (only if !LAST)

    int tid  = threadIdx.x;
    int lane = tid & 31;
    int wid  = tid >> 5;
    int wm   = wid >> 2;
    int wn   = wid & 3;
    int grp  = lane >> 2;
    int thr4 = lane & 3;
    int r0   = blockIdx.x * BM;

    // stage A (fp16, 128 rows x 256B = 16 chunks/row) via cp.async
    #pragma unroll
    for (int j = 0; j < 8; j++) {
        int cidx = tid + j * 256;          // 0..2047
        int row  = cidx >> 4;
        int c16  = cidx & 15;
        int gr   = r0 + row;
        int grc  = gr < M ? gr : 0;
        const __half* gp = A + (size_t)grc * H + c16 * 8;
        unsigned sa = (unsigned)__cvta_generic_to_shared(Ah + row * TS_STRIDE + c16 * 8);
        cp_async16(sa, gp, (gr < M) ? 16 : 0);
    }
    asm volatile("cp.async.commit_group;");

    // stage W2 transposed fp16: W2t[n][k] = W2[k][n]
    #pragma unroll
    for (int i = tid; i < 128 * 64; i += 256) {
        int k  = i >> 6;
        int n2 = (i & 63) * 2;
        float2 v = *(const float2*)(W2 + (size_t)k * H + n2);
        W2t[(size_t)n2 * TS_STRIDE + k]       = __float2half_rn(v.x);
        W2t[(size_t)(n2 + 1) * TS_STRIDE + k] = __float2half_rn(v.y);
    }
    if constexpr (!LAST) {
        #pragma unroll
        for (int i = tid; i < 128 * 64; i += 256) {
            int k  = i >> 6;
            int n2 = (i & 63) * 2;
            float2 v = *(const float2*)(W1 + (size_t)k * H + n2);
            W1t[(size_t)n2 * TS_STRIDE + k]       = __float2half_rn(v.x);
            W1t[(size_t)(n2 + 1) * TS_STRIDE + k] = __float2half_rn(v.y);
        }
    }
    asm volatile("cp.async.wait_group 0;" ::: "memory");
    __syncthreads();

    // ---- GEMM1: Ah @ W2t^T (fp16) ----
    float c[4][4][4];
    #pragma unroll
    for (int i = 0; i < 4; i++)
        #pragma unroll
        for (int j = 0; j < 4; j++)
            #pragma unroll
            for (int r = 0; r < 4; r++) c[i][j][r] = 0.f;

    #pragma unroll
    for (int kc = 0; kc < 8; kc++) {
        unsigned a[4][4];
        #pragma unroll
        for (int am = 0; am < 4; am++) {
            const __half* tb = Ah + (size_t)(wm * 64 + am * 16 + grp) * TS_STRIDE + kc * 16 + 2 * thr4;
            a[am][0] = *(const unsigned*)tb;
            a[am][1] = *(const unsigned*)(tb + 8 * TS_STRIDE);
            a[am][2] = *(const unsigned*)(tb + 8);
            a[am][3] = *(const unsigned*)(tb + 8 * TS_STRIDE + 8);
        }
        unsigned b[4][2];
        #pragma unroll
        for (int an = 0; an < 4; an++) {
            const __half* bb = W2t + (size_t)(wn * 32 + an * 8 + grp) * TS_STRIDE + kc * 16 + 2 * thr4;
            b[an][0] = *(const unsigned*)bb;
            b[an][1] = *(const unsigned*)(bb + 8);
        }
        #pragma unroll
        for (int am = 0; am < 4; am++)
            #pragma unroll
            for (int an = 0; an < 4; an++) {
                asm volatile(
                    "mma.sync.aligned.m16n8k16.row.col.f32.f16.f16.f32 "
                    "{%0,%1,%2,%3}, {%4,%5,%6,%7}, {%8,%9}, {%0,%1,%2,%3};"
                    : "+f"(c[am][an][0]), "+f"(c[am][an][1]),
                      "+f"(c[am][an][2]), "+f"(c[am][an][3])
                    : "r"(a[am][0]), "r"(a[am][1]), "r"(a[am][2]), "r"(a[am][3]),
                      "r"(b[an][0]), "r"(b[an][1]));
            }
    }

    if constexpr (LAST) {
        #pragma unroll
        for (int an = 0; an < 4; an++) {
            int col = wn * 32 + an * 8 + 2 * thr4;
            float2 bv = *(const float2*)(b2 + col);
            #pragma unroll
            for (int am = 0; am < 4; am++) {
                int row0 = r0 + wm * 64 + am * 16 + grp;
                if (row0 < M)
                    *(__half2*)(P + (size_t)row0 * H + col) =
                        __floats2half2_rn(fmaxf(c[am][an][0] + bv.x, 0.f),
                                          fmaxf(c[am][an][1] + bv.y, 0.f));
                if (row0 + 8 < M)
                    *(__half2*)(P + (size_t)(row0 + 8) * H + col) =
                        __floats2half2_rn(fmaxf(c[am][an][2] + bv.x, 0.f),
                                          fmaxf(c[am][an][3] + bv.y, 0.f));
            }
        }
        return;
    }

    __syncthreads();   // everyone done reading Ah

    // relu+b2 -> Ts (reuse Ah region)
    #pragma unroll
    for (int an = 0; an < 4; an++) {
        int col = wn * 32 + an * 8 + 2 * thr4;
        float2 bv = *(const float2*)(b2 + col);
        #pragma unroll
        for (int am = 0; am < 4; am++) {
            int r = wm * 64 + am * 16 + grp;
            *(__half2*)(Ah + (size_t)r * TS_STRIDE + col) =
                __floats2half2_rn(fmaxf(c[am][an][0] + bv.x, 0.f),
                                  fmaxf(c[am][an][1] + bv.y, 0.f));
            *(__half2*)(Ah + (size_t)(r + 8) * TS_STRIDE + col) =
                __floats2half2_rn(fmaxf(c[am][an][2] + bv.x, 0.f),
                                  fmaxf(c[am][an][3] + bv.y, 0.f));
        }
    }
    __syncthreads();

    // ---- GEMM2: Ts @ W1t^T (fp16) ----
    float p[4][4][4];
    #pragma unroll
    for (int i = 0; i < 4; i++)
        #pragma unroll
        for (int j = 0; j < 4; j++)
            #pragma unroll
            for (int r = 0; r < 4; r++) p[i][j][r] = 0.f;

    #pragma unroll
    for (int kc = 0; kc < 8; kc++) {
        unsigned a[4][4];
        #pragma unroll
        for (int am = 0; am < 4; am++) {
            const __half* tb = Ah + (size_t)(wm * 64 + am * 16 + grp) * TS_STRIDE + kc * 16 + 2 * thr4;
            a[am][0] = *(const unsigned*)tb;
            a[am][1] = *(const unsigned*)(tb + 8 * TS_STRIDE);
            a[am][2] = *(const unsigned*)(tb + 8);
            a[am][3] = *(const unsigned*)(tb + 8 * TS_STRIDE + 8);
        }
        unsigned b[4][2];
        #pragma unroll
        for (int an = 0; an < 4; an++) {
            const __half* bb = W1t + (size_t)(wn * 32 + an * 8 + grp) * TS_STRIDE + kc * 16 + 2 * thr4;
            b[an][0] = *(const unsigned*)bb;
            b[an][1] = *(const unsigned*)(bb + 8);
        }
        #pragma unroll
        for (int am = 0; am < 4; am++)
            #pragma unroll
            for (int an = 0; an < 4; an++) {
                asm volatile(
                    "mma.sync.aligned.m16n8k16.row.col.f32.f16.f16.f32 "
                    "{%0,%1,%2,%3}, {%4,%5,%6,%7}, {%8,%9}, {%0,%1,%2,%3};"
                    : "+f"(p[am][an][0]), "+f"(p[am][an][1]),
                      "+f"(p[am][an][2]), "+f"(p[am][an][3])
                    : "r"(a[am][0]), "r"(a[am][1]), "r"(a[am][2]), "r"(a[am][3]),
                      "r"(b[an][0]), "r"(b[an][1]));
            }
    }

    #pragma unroll
    for (int an = 0; an < 4; an++) {
        int col = wn * 32 + an * 8 + 2 * thr4;
        float2 bv = *(const float2*)(b1 + col);
        #pragma unroll
        for (int am = 0; am < 4; am++) {
            int row0 = r0 + wm * 64 + am * 16 + grp;
            if (row0 < M)
                *(__half2*)(P + (size_t)row0 * H + col) =
                    __floats2half2_rn(p[am][an][0] + bv.x, p[am][an][1] + bv.y);
            if (row0 + 8 < M)
                *(__half2*)(P + (size_t)(row0 + 8) * H + col) =
                    __floats2half2_rn(p[am][an][2] + bv.x, p[am][an][3] + bv.y);
        }
    }
}

// ---------------- CSR aggregation: warp per dst node, 2 edges/iter, deep prefetch ----------------
__global__ void agg_kernel(const __half* __restrict__ table,
                           const __half* __restrict__ proj,
                           const int*   __restrict__ rowptr,
                           const int*   __restrict__ srcs,
                           const float* __restrict__ dists,
                           __half*      __restrict__ agg, int N) {
    int n = blockIdx.x * 8 + (threadIdx.x >> 5);
    if (n >= N) return;
    int lane = threadIdx.x & 31;

    int beg = __ldg(rowptr + n);
    int end = __ldg(rowptr + n + 1);

    float ax = 0.f, ay = 0.f, az = 0.f, aw = 0.f;

    auto ldidx = [&](int j, int& s, int& k, float& fr) {
        s = __ldg(srcs + j);
        float d = __ldg(dists + j);
        float pos = d * (float)(TAB - 1);
        int kk = (int)pos;
        kk = min(max(kk, 0), TAB - 2);
        fr = pos - (float)kk;
        k = kk;
    };

    int sA = 0, kA = 0, sB = 0, kB = 0;
    float frA = 0.f, frB = 0.f;
    if (beg < end)     ldidx(beg,     sA, kA, frA);
    if (beg + 1 < end) ldidx(beg + 1, sB, kB, frB);

    for (int i = beg; i < end; i += 2) {
        bool has2 = (i + 1 < end);
        // prefetch indices for next pair
        int sC = 0, kC = 0, sD = 0, kD = 0;
        float frC = 0.f, frD = 0.f;
        if (i + 2 < end) ldidx(i + 2, sC, kC, frC);
        if (i + 3 < end) ldidx(i + 3, sD, kD, frD);

        // issue all payload loads for edge A (and B) before consuming
        const uint2* tA = (const uint2*)(table + (size_t)kA * H) + lane;
        uint2 q0A = __ldg(tA);
        uint2 q1A = __ldg(tA + (H / 4));
        uint2 hpA = __ldg((const uint2*)(proj + (size_t)sA * H) + lane);
        uint2 q0B, q1B, hpB;
        if (has2) {
            const uint2* tB = (const uint2*)(table + (size_t)kB * H) + lane;
            q0B = __ldg(tB);
            q1B = __ldg(tB + (H / 4));
            hpB = __ldg((const uint2*)(proj + (size_t)sB * H) + lane);
        }

        {
            float2 f0a = __half22float2(*(const __half2*)&q0A.x);
            float2 f0b = __half22float2(*(const __half2*)&q0A.y);
            float2 f1a = __half22float2(*(const __half2*)&q1A.x);
            float2 f1b = __half22float2(*(const __half2*)&q1A.y);
            float2 p01 = __half22float2(*(const __half2*)&hpA.x);
            float2 p23 = __half22float2(*(const __half2*)&hpA.y);
            ax = fmaf((f0a.x + frA * (f1a.x - f0a.x)), p01.x, ax);
            ay = fmaf((f0a.y + frA * (f1a.y - f0a.y)), p01.y, ay);
            az = fmaf((f0b.x + frA * (f1b.x - f0b.x)), p23.x, az);
            aw = fmaf((f0b.y + frA * (f1b.y - f0b.y)), p23.y, aw);
        }
        if (has2) {
            float2 f0a = __half22float2(*(const __half2*)&q0B.x);
            float2 f0b = __half22float2(*(const __half2*)&q0B.y);
            float2 f1a = __half22float2(*(const __half2*)&q1B.x);
            float2 f1b = __half22float2(*(const __half2*)&q1B.y);
            float2 p01 = __half22float2(*(const __half2*)&hpB.x);
            float2 p23 = __half22float2(*(const __half2*)&hpB.y);
            ax = fmaf((f0a.x + frB * (f1a.x - f0a.x)), p01.x, ax);
            ay = fmaf((f0a.y + frB * (f1a.y - f0a.y)), p01.y, ay);
            az = fmaf((f0b.x + frB * (f1b.x - f0b.x)), p23.x, az);
            aw = fmaf((f0b.y + frB * (f1b.y - f0b.y)), p23.y, aw);
        }

        sA = sC; kA = kC; frA = frC;
        sB = sD; kB = kD; frB = frD;
    }

    uint2 o;
    __half2 h01 = __floats2half2_rn(ax, ay);
    __half2 h23 = __floats2half2_rn(az, aw);
    o.x = *(unsigned*)&h01;
    o.y = *(unsigned*)&h23;
    *(uint2*)(agg + (size_t)n * H + lane * 4) = o;
}

// ---------------- graph pooling (sum + count), fp16 input ----------------
__global__ void pool_kernel(const __half* __restrict__ cur, const int* __restrict__ gid, int N) {
    int n = blockIdx.x * 8 + (threadIdx.x >> 5);
    if (n >= N) return;
    int lane = threadIdx.x & 31;
    int g = __ldg(gid + n);
    uint2 hv = __ldg((const uint2*)(cur + (size_t)n * H) + lane);
    float2 v01 = __half22float2(*(const __half2*)&hv.x);
    float2 v23 = __half22float2(*(const __half2*)&hv.y);
    float* p = g_pool + (size_t)g * H + lane * 4;
    asm volatile("red.global.add.v4.f32 [%0], {%1,%2,%3,%4};"
                 :: "l"(p), "f"(v01.x), "f"(v01.y), "f"(v23.x), "f"(v23.y) : "memory");
    if (lane == 0) atomicAdd(&g_cnt[g], 1.0f);
}

// ---------------- readout: mean, FC, log_softmax ----------------
__global__ void readout_kernel(const float* __restrict__ fcw, const float* __restrict__ fcb,
                               float* __restrict__ out) {
    int g = blockIdx.x;
    int t = threadIdx.x;    // 128
    __shared__ float p[H];
    __shared__ float logits[C_OUT];

    float c = fmaxf(g_cnt[g], 1.0f);
    p[t] = g_pool[(size_t)g * H + t] / c;
    __syncthreads();

    if (t < C_OUT) {
        float acc = fcb[t];
        #pragma unroll 8
        for (int h = 0; h < H; h++) acc = fmaf(p[h], fcw[h * C_OUT + t], acc);
        logits[t] = acc;
    }
    __syncthreads();

    if (t == 0) {
        float mx = -1e30f;
        for (int i = 0; i < C_OUT; i++) mx = fmaxf(mx, logits[i]);
        float se = 0.f;
        for (int i = 0; i < C_OUT; i++) se += expf(logits[i] - mx);
        float lse = mx + logf(se);
        for (int i = 0; i < C_OUT; i++) out[g * C_OUT + i] = logits[i] - lse;
    }
}

// ---------------- launch ----------------
extern "C" void kernel_launch(void* const* d_in, const int* in_sizes, int n_in,
                              void* d_out, int out_size) {
    const float* x         = (const float*)d_in[0];
    const float* edge_dist = (const float*)d_in[1];
    const int*   esrc      = (const int*)  d_in[2];
    const int*   edst      = (const int*)  d_in[3];
    const int*   gid       = (const int*)  d_in[4];
    const float* W1_0      = (const float*)d_in[5];
    const float* b1_0      = (const float*)d_in[6];
    const float* W1_rest   = (const float*)d_in[7];
    const float* b1_rest   = (const float*)d_in[8];
    const float* Wf1       = (const float*)d_in[9];
    const float* bf1       = (const float*)d_in[10];
    const float* Wf2       = (const float*)d_in[11];
    const float* bf2       = (const float*)d_in[12];
    const float* W2        = (const float*)d_in[13];
    const float* b2        = (const float*)d_in[14];
    const float* fcw       = (const float*)d_in[15];
    const float* fcb       = (const float*)d_in[16];
    float* out = (float*)d_out;

    int E = in_sizes[1];
    int N = in_sizes[4];

    __half *proj, *agg, *table, *cur;
    int *rowptr, *src_s;
    float *dist_s;
    cudaGetSymbolAddress((void**)&proj,   g_proj);
    cudaGetSymbolAddress((void**)&agg,    g_agg);
    cudaGetSymbolAddress((void**)&cur,    g_cur);
    cudaGetSymbolAddress((void**)&table,  g_table);
    cudaGetSymbolAddress((void**)&rowptr, g_rowptr);
    cudaGetSymbolAddress((void**)&src_s,  g_src_s);
    cudaGetSymbolAddress((void**)&dist_s, g_dist_s);

    const int smem64   = (64 * BS_STRIDE + 2 * BM * AS_STRIDE) * 4;
    const int smemL    = 3 * 128 * TS_STRIDE * 2;   // 104448
    const int smemLast = 2 * 128 * TS_STRIDE * 2;
    const int smemTab  = (H * H + 2 * TROWS * H) * 4;
    cudaFuncSetAttribute(gemm_tf32<F_IN>,
                         cudaFuncAttributeMaxDynamicSharedMemorySize, smem64);
    cudaFuncSetAttribute(layer_gemm<false>,
                         cudaFuncAttributeMaxDynamicSharedMemorySize, smemL);
    cudaFuncSetAttribute(layer_gemm<true>,
                         cudaFuncAttributeMaxDynamicSharedMemorySize, smemLast);
    cudaFuncSetAttribute(table_kernel,
                         cudaFuncAttributeMaxDynamicSharedMemorySize, smemTab);

    // build per-layer filter tables
    table_kernel<<<L_LAYERS * (TAB / TROWS), H, smemTab>>>(Wf1, bf1, Wf2, bf2);

    // build CSR by dst
    int nb = (N + 1023) / 1024;
    deg_zero_kernel<<<(N + 255) / 256, 256>>>(N);
    deg_count_kernel<<<(E + 255) / 256, 256>>>(edst, E);
    scan_bsum_kernel<<<nb, 1024>>>(N);
    scan_boff_kernel<<<1, 64>>>(nb, E);
    scan_final_kernel<<<nb, 1024>>>(N);
    scatter_kernel<<<(E + 255) / 256, 256>>>(esrc, edst, edge_dist, E);

    int gemm_blocks = (N + BM - 1) / BM;
    int agg_blocks  = (N + 7) / 8;

    // initial projection: proj = x @ W1_0 + b1_0 (fp16 out)
    gemm_tf32<F_IN><<<gemm_blocks, 256, smem64>>>(x, W1_0, b1_0, proj, N);

    for (int l = 0; l < L_LAYERS; l++) {
        agg_kernel<<<agg_blocks, 256>>>(table + (size_t)l * TAB * H,
                                        proj, rowptr, src_s, dist_s, agg, N);

        if (l < L_LAYERS - 1) {
            layer_gemm<false><<<gemm_blocks, 256, smemL>>>(
                agg,
                W2 + (size_t)l * H * H, b2 + (size_t)l * H,
                W1_rest + (size_t)l * H * H, b1_rest + (size_t)l * H,
                proj, N);
        } else {
            layer_gemm<true><<<gemm_blocks, 256, smemLast>>>(
                agg, W2 + (size_t)l * H * H, b2 + (size_t)l * H,
                nullptr, nullptr, cur, N);
        }
    }

    // graph mean pooling + FC + log_softmax
    zero_pool_kernel<<<(G_GRAPHS * H + 255) / 256, 256>>>();
    pool_kernel<<<(N + 7) / 8, 256>>>(cur, gid, N);
    readout_kernel<<<G_GRAPHS, H>>>(fcw, fcb, out);
}